// round 3
// baseline (speedup 1.0000x reference)
#include <cuda_runtime.h>
#include <math.h>

#define N_NODES 50000
#define D_FEAT  364
#define D_OUT   150
#define N_PAIRS 8192
#define N_EDGES 200000
#define NEG_SLOPE 0.01f

#define BM 64
#define BN 64
#define BK 16

// Scratch (no cudaMalloc allowed). ~228 MB total. 16B-aligned for float4.
__device__ __align__(16) float g_agg[(size_t)N_NODES * D_FEAT];
__device__ __align__(16) float g_h1 [(size_t)N_NODES * D_FEAT];
__device__ __align__(16) float g_h2 [(size_t)N_NODES * D_FEAT];
__device__ __align__(16) float g_z  [(size_t)2 * N_PAIRS * D_OUT];

// ---------------------------------------------------------------------------
// zero g_agg
__global__ void zero_agg_kernel() {
    size_t n4 = (size_t)N_NODES * D_FEAT / 4;
    size_t i = (size_t)blockIdx.x * blockDim.x + threadIdx.x;
    if (i < n4) reinterpret_cast<float4*>(g_agg)[i] = make_float4(0.f, 0.f, 0.f, 0.f);
}

// ---------------------------------------------------------------------------
// scatter: g_agg[dst] += x[src], one warp per edge
// layer==0: x = x_ext (features); layer==1: x = g_h1
__global__ void scatter_kernel(const float* __restrict__ x_ext,
                               const int* __restrict__ src,
                               const int* __restrict__ dst,
                               int layer) {
    int warp = (blockIdx.x * blockDim.x + threadIdx.x) >> 5;
    int lane = threadIdx.x & 31;
    if (warp >= N_EDGES) return;
    const float* __restrict__ x = (layer == 0) ? x_ext : g_h1;
    int s = src[warp];
    int d = dst[warp];
    const float4* xs = reinterpret_cast<const float4*>(x + (size_t)s * D_FEAT);
    float* ad = g_agg + (size_t)d * D_FEAT;
    #pragma unroll
    for (int i = lane; i < D_FEAT / 4; i += 32) {   // 91 float4 -> 3 iters
        float4 v = xs[i];
        atomicAdd(ad + i * 4 + 0, v.x);
        atomicAdd(ad + i * 4 + 1, v.y);
        atomicAdd(ad + i * 4 + 2, v.z);
        atomicAdd(ad + i * 4 + 3, v.w);
    }
}

// ---------------------------------------------------------------------------
// out = lrelu((g_agg + x) @ W + b)   [M=N_NODES, K=N=D_FEAT]
// x_is_ext: x = x_ext (features) else g_h1.  out_sel: 0 -> g_h1, 1 -> g_h2.
__global__ __launch_bounds__(256) void gemm_nodes_kernel(
        const float* __restrict__ x_ext, int x_is_ext,
        const float* __restrict__ W, const float* __restrict__ bias,
        int out_sel) {
    const int M = N_NODES, K = D_FEAT, N = D_FEAT;
    const float* __restrict__ x = x_is_ext ? x_ext : g_h1;
    float* __restrict__ out = out_sel ? g_h2 : g_h1;

    __shared__ __align__(16) float As[BK][BM];
    __shared__ __align__(16) float Bs[BK][BN];

    int bm = blockIdx.y * BM;
    int bn = blockIdx.x * BN;
    int tid = threadIdx.x;
    int tx = tid & 15, ty = tid >> 4;

    int a_row = tid >> 2;          // 0..63
    int a_k4  = (tid & 3) * 4;     // 0,4,8,12
    int b_row = tid >> 4;          // 0..15
    int b_c4  = (tid & 15) * 4;    // 0..60

    float acc[4][4] = {};

    for (int k0 = 0; k0 < K; k0 += BK) {
        // A tile (residual fused). Row stride 364 floats = 1456 B (16B multiple),
        // a_k4 multiple of 4 floats -> float4 offsets always 16B aligned.
        {
            int gm = bm + a_row;
            int gk = k0 + a_k4;
            float4 v = make_float4(0.f, 0.f, 0.f, 0.f);
            if (gm < M) {
                if (gk + 3 < K) {
                    float4 va = *reinterpret_cast<const float4*>(g_agg + (size_t)gm * K + gk);
                    float4 vx = *reinterpret_cast<const float4*>(x     + (size_t)gm * K + gk);
                    v = make_float4(va.x + vx.x, va.y + vx.y, va.z + vx.z, va.w + vx.w);
                } else {
                    #pragma unroll
                    for (int j = 0; j < 4; j++) {
                        int kk = gk + j;
                        reinterpret_cast<float*>(&v)[j] =
                            (kk < K) ? g_agg[(size_t)gm * K + kk] + x[(size_t)gm * K + kk] : 0.f;
                    }
                }
            }
            As[a_k4 + 0][a_row] = v.x;
            As[a_k4 + 1][a_row] = v.y;
            As[a_k4 + 2][a_row] = v.z;
            As[a_k4 + 3][a_row] = v.w;
        }
        // B tile: W row stride 364 floats = 1456 B (16B multiple) -> float4 OK.
        {
            int gk = k0 + b_row;
            int gn = bn + b_c4;
            float4 v = make_float4(0.f, 0.f, 0.f, 0.f);
            if (gk < K) {
                if (gn + 3 < N) {
                    v = *reinterpret_cast<const float4*>(W + (size_t)gk * N + gn);
                } else {
                    #pragma unroll
                    for (int j = 0; j < 4; j++) {
                        int nn = gn + j;
                        reinterpret_cast<float*>(&v)[j] = (nn < N) ? W[(size_t)gk * N + nn] : 0.f;
                    }
                }
            }
            *reinterpret_cast<float4*>(&Bs[b_row][b_c4]) = v;
        }
        __syncthreads();

        #pragma unroll
        for (int k = 0; k < BK; k++) {
            float4 a4 = *reinterpret_cast<const float4*>(&As[k][ty * 4]);
            float4 b4 = *reinterpret_cast<const float4*>(&Bs[k][tx * 4]);
            float a[4] = {a4.x, a4.y, a4.z, a4.w};
            float bb[4] = {b4.x, b4.y, b4.z, b4.w};
            #pragma unroll
            for (int i = 0; i < 4; i++)
                #pragma unroll
                for (int j = 0; j < 4; j++)
                    acc[i][j] += a[i] * bb[j];
        }
        __syncthreads();
    }

    #pragma unroll
    for (int i = 0; i < 4; i++) {
        int gm = bm + ty * 4 + i;
        if (gm >= M) continue;
        #pragma unroll
        for (int j = 0; j < 4; j++) {
            int gn = bn + tx * 4 + j;
            if (gn >= N) continue;
            float c = acc[i][j] + bias[gn];
            out[(size_t)gm * N + gn] = c > 0.f ? c : NEG_SLOPE * c;
        }
    }
}

// ---------------------------------------------------------------------------
// g_z = lrelu(g_h2[vcat] @ W3 + b3)  [M=2*N_PAIRS, K=D_FEAT, N=D_OUT]
// NOTE: W3 has N=150 -> row stride 600 B == 8 mod 16, so float4 loads on W3
// are MISALIGNED for odd k rows (this was the harness fault). Use float2
// (600 and gn*4 are both multiples of 8 -> always 8B aligned).
__global__ __launch_bounds__(256) void gemm_pairs_kernel(
        const int* __restrict__ v1, const int* __restrict__ v2,
        const float* __restrict__ W, const float* __restrict__ bias) {
    const int K = D_FEAT, N = D_OUT;

    __shared__ __align__(16) float As[BK][BM];
    __shared__ __align__(16) float Bs[BK][BN];
    __shared__ int rows[BM];

    int bm = blockIdx.y * BM;
    int bn = blockIdx.x * BN;
    int tid = threadIdx.x;
    int tx = tid & 15, ty = tid >> 4;

    if (tid < BM) {
        int gm = bm + tid;   // M divisible by BM
        rows[tid] = (gm < N_PAIRS) ? v1[gm] : v2[gm - N_PAIRS];
    }
    __syncthreads();

    int a_row = tid >> 2;
    int a_k4  = (tid & 3) * 4;
    int b_row = tid >> 4;
    int b_c4  = (tid & 15) * 4;

    float acc[4][4] = {};

    for (int k0 = 0; k0 < K; k0 += BK) {
        // A tile: g_h2 row stride 1456 B -> float4 safe.
        {
            int node = rows[a_row];
            int gk = k0 + a_k4;
            float4 v = make_float4(0.f, 0.f, 0.f, 0.f);
            if (gk + 3 < K) {
                v = *reinterpret_cast<const float4*>(g_h2 + (size_t)node * K + gk);
            } else {
                #pragma unroll
                for (int j = 0; j < 4; j++) {
                    int kk = gk + j;
                    reinterpret_cast<float*>(&v)[j] = (kk < K) ? g_h2[(size_t)node * K + kk] : 0.f;
                }
            }
            As[a_k4 + 0][a_row] = v.x;
            As[a_k4 + 1][a_row] = v.y;
            As[a_k4 + 2][a_row] = v.z;
            As[a_k4 + 3][a_row] = v.w;
        }
        // B tile: float2 x2 loads (8B-aligned always).
        {
            int gk = k0 + b_row;
            int gn = bn + b_c4;
            float4 v = make_float4(0.f, 0.f, 0.f, 0.f);
            if (gk < K) {
                const float* wrow = W + (size_t)gk * N;
                if (gn + 3 < N) {
                    float2 lo = *reinterpret_cast<const float2*>(wrow + gn);
                    float2 hi = *reinterpret_cast<const float2*>(wrow + gn + 2);
                    v = make_float4(lo.x, lo.y, hi.x, hi.y);
                } else {
                    #pragma unroll
                    for (int j = 0; j < 4; j++) {
                        int nn = gn + j;
                        reinterpret_cast<float*>(&v)[j] = (nn < N) ? wrow[nn] : 0.f;
                    }
                }
            }
            *reinterpret_cast<float4*>(&Bs[b_row][b_c4]) = v;
        }
        __syncthreads();

        #pragma unroll
        for (int k = 0; k < BK; k++) {
            float4 a4 = *reinterpret_cast<const float4*>(&As[k][ty * 4]);
            float4 b4 = *reinterpret_cast<const float4*>(&Bs[k][tx * 4]);
            float a[4] = {a4.x, a4.y, a4.z, a4.w};
            float bb[4] = {b4.x, b4.y, b4.z, b4.w};
            #pragma unroll
            for (int i = 0; i < 4; i++)
                #pragma unroll
                for (int j = 0; j < 4; j++)
                    acc[i][j] += a[i] * bb[j];
        }
        __syncthreads();
    }

    #pragma unroll
    for (int i = 0; i < 4; i++) {
        int gm = bm + ty * 4 + i;
        #pragma unroll
        for (int j = 0; j < 4; j++) {
            int gn = bn + tx * 4 + j;
            if (gn >= N) continue;
            float c = acc[i][j] + bias[gn];
            g_z[(size_t)gm * N + gn] = c > 0.f ? c : NEG_SLOPE * c;
        }
    }
}

// ---------------------------------------------------------------------------
// L2 normalize each row of g_z -> out, one warp per row (scalar accesses only)
__global__ void normalize_kernel(float* __restrict__ out) {
    int row  = (blockIdx.x * blockDim.x + threadIdx.x) >> 5;
    int lane = threadIdx.x & 31;
    if (row >= 2 * N_PAIRS) return;
    const float* zr = g_z + (size_t)row * D_OUT;
    float ss = 0.f;
    for (int i = lane; i < D_OUT; i += 32) { float v = zr[i]; ss += v * v; }
    #pragma unroll
    for (int o = 16; o; o >>= 1) ss += __shfl_xor_sync(0xFFFFFFFFu, ss, o);
    float norm = sqrtf(ss);
    float inv = 1.f / fmaxf(norm, 1e-12f);
    for (int i = lane; i < D_OUT; i += 32) out[(size_t)row * D_OUT + i] = zr[i] * inv;
}

// ---------------------------------------------------------------------------
extern "C" void kernel_launch(void* const* d_in, const int* in_sizes, int n_in,
                              void* d_out, int out_size) {
    const float* features = (const float*)d_in[0];
    const int*   src      = (const int*)  d_in[1];
    const int*   dst      = (const int*)  d_in[2];
    const int*   v1       = (const int*)  d_in[3];
    const int*   v2       = (const int*)  d_in[4];
    const float* W1       = (const float*)d_in[5];
    const float* b1       = (const float*)d_in[6];
    const float* W2       = (const float*)d_in[7];
    const float* b2       = (const float*)d_in[8];
    const float* W3       = (const float*)d_in[9];
    const float* b3       = (const float*)d_in[10];
    float* out = (float*)d_out;
    (void)in_sizes; (void)n_in; (void)out_size;

    const size_t n4 = (size_t)N_NODES * D_FEAT / 4;
    int zero_blocks = (int)((n4 + 255) / 256);
    int scat_blocks = (N_EDGES * 32 + 255) / 256;   // one warp per edge

    dim3 gemm_nodes_grid((D_FEAT + BN - 1) / BN, (N_NODES + BM - 1) / BM);
    dim3 gemm_pairs_grid((D_OUT + BN - 1) / BN, (2 * N_PAIRS) / BM);

    // layer 1
    zero_agg_kernel<<<zero_blocks, 256>>>();
    scatter_kernel<<<scat_blocks, 256>>>(features, src, dst, 0);
    gemm_nodes_kernel<<<gemm_nodes_grid, 256>>>(features, 1, W1, b1, /*out_sel=*/0);

    // layer 2
    zero_agg_kernel<<<zero_blocks, 256>>>();
    scatter_kernel<<<scat_blocks, 256>>>(features, src, dst, 1);
    gemm_nodes_kernel<<<gemm_nodes_grid, 256>>>(nullptr, 0, W2, b2, /*out_sel=*/1);

    // pair projection + normalize
    gemm_pairs_kernel<<<gemm_pairs_grid, 256>>>(v1, v2, W3, b3);
    normalize_kernel<<<(2 * N_PAIRS * 32 + 255) / 256, 256>>>(out);
}

// round 4
// speedup vs baseline: 1.3262x; 1.3262x over previous
#include <cuda_runtime.h>
#include <math.h>
#include <stdint.h>

#define N_NODES 50000
#define D_FEAT  364
#define D_OUT   150
#define N_PAIRS 8192
#define N_EDGES 200000
#define NEG_SLOPE 0.01f

// Scratch (no cudaMalloc allowed). 16B-aligned for float4.
__device__ __align__(16) float g_agg[(size_t)N_NODES * D_FEAT];
__device__ __align__(16) float g_h1 [(size_t)N_NODES * D_FEAT];
__device__ __align__(16) float g_h2 [(size_t)N_NODES * D_FEAT];
__device__ __align__(16) float g_z  [(size_t)2 * N_PAIRS * D_OUT];

// ---------------------------------------------------------------------------
// g_agg = x  (residual folded into aggregation buffer)
__global__ void copy_to_agg_kernel(const float* __restrict__ x_ext, int use_ext) {
    size_t n4 = (size_t)N_NODES * D_FEAT / 4;
    size_t i = (size_t)blockIdx.x * blockDim.x + threadIdx.x;
    if (i >= n4) return;
    const float4* s = use_ext ? reinterpret_cast<const float4*>(x_ext)
                              : reinterpret_cast<const float4*>(g_h1);
    reinterpret_cast<float4*>(g_agg)[i] = s[i];
}

// ---------------------------------------------------------------------------
// scatter: g_agg[dst] += x[src], one warp per edge
__global__ void scatter_kernel(const float* __restrict__ x_ext,
                               const int* __restrict__ src,
                               const int* __restrict__ dst,
                               int layer) {
    int warp = (blockIdx.x * blockDim.x + threadIdx.x) >> 5;
    int lane = threadIdx.x & 31;
    if (warp >= N_EDGES) return;
    const float* __restrict__ x = (layer == 0) ? x_ext : g_h1;
    int s = src[warp];
    int d = dst[warp];
    const float4* xs = reinterpret_cast<const float4*>(x + (size_t)s * D_FEAT);
    float* ad = g_agg + (size_t)d * D_FEAT;
    #pragma unroll
    for (int i = lane; i < D_FEAT / 4; i += 32) {   // 91 float4 -> 3 iters
        float4 v = xs[i];
        atomicAdd(ad + i * 4 + 0, v.x);
        atomicAdd(ad + i * 4 + 1, v.y);
        atomicAdd(ad + i * 4 + 2, v.z);
        atomicAdd(ad + i * 4 + 3, v.w);
    }
}

// ---------------------------------------------------------------------------
// tf32 helpers
__device__ __forceinline__ uint32_t f2tf32(float x) {
    uint32_t r;
    asm("cvt.rna.tf32.f32 %0, %1;" : "=r"(r) : "f"(x));
    return r;
}
__device__ __forceinline__ void split_tf32(float v, float& h, float& l) {
    h = __uint_as_float(f2tf32(v));
    l = __uint_as_float(f2tf32(v - h));
}
__device__ __forceinline__ void mma8(float d[4], const uint32_t a[4], const uint32_t b[2]) {
    asm volatile(
        "mma.sync.aligned.m16n8k8.row.col.f32.tf32.tf32.f32 "
        "{%0,%1,%2,%3}, {%4,%5,%6,%7}, {%8,%9}, {%0,%1,%2,%3};\n"
        : "+f"(d[0]), "+f"(d[1]), "+f"(d[2]), "+f"(d[3])
        : "r"(a[0]), "r"(a[1]), "r"(a[2]), "r"(a[3]), "r"(b[0]), "r"(b[1]));
}

// ---------------------------------------------------------------------------
// out = lrelu(g_agg @ W + b) using 3xTF32 tensor-core GEMM.
// A = g_agg (already contains agg + x). M=N_NODES, K=N=D_FEAT.
// Tile: BM=128, BN=64, BK=32. 256 threads = 8 warps (4 m x 2 n), warp 32x32.
#define TC_BM 128
#define TC_BN 64
#define TC_BK 32
#define AS_STRIDE 36   // == 4 mod 32 -> conflict-free frag LDS
#define BS_STRIDE 72   // == 8 mod 32 -> conflict-free frag LDS
#define SMEM_FLOATS (2 * TC_BM * AS_STRIDE + 2 * TC_BK * BS_STRIDE)  // 13824

__global__ __launch_bounds__(256) void gemm_nodes_tc(
        const float* __restrict__ W, const float* __restrict__ bias, int out_sel) {
    const int M = N_NODES, K = D_FEAT, N = D_FEAT;
    float* __restrict__ out = out_sel ? g_h2 : g_h1;

    extern __shared__ float smf[];
    float* As_h = smf;                                 // [128][36]
    float* As_l = smf + TC_BM * AS_STRIDE;             // [128][36]
    float* Bs_h = smf + 2 * TC_BM * AS_STRIDE;         // [32][72]
    float* Bs_l = Bs_h + TC_BK * BS_STRIDE;            // [32][72]

    int bm = blockIdx.y * TC_BM;
    int bn = blockIdx.x * TC_BN;
    int tid = threadIdx.x;
    int lane = tid & 31;
    int wid = tid >> 5;
    int wm = (wid & 3) * 32;
    int wn = (wid >> 2) * 32;
    int r = lane >> 2;     // 0..7
    int c = lane & 3;      // 0..3

    float acc[2][4][4];
    #pragma unroll
    for (int i = 0; i < 2; i++)
        #pragma unroll
        for (int j = 0; j < 4; j++)
            #pragma unroll
            for (int q = 0; q < 4; q++) acc[i][j][q] = 0.f;

    int ak4 = tid & 7;      // float4 index along k
    int arl = tid >> 3;     // 0..31 row
    int bn4 = tid & 15;     // float4 index along n
    int bkr = tid >> 4;     // 0..15 k row

    for (int k0 = 0; k0 < K; k0 += TC_BK) {
        // ---- load A tile [128 x 32], split hi/lo, STS.128 (phase conflict-free)
        #pragma unroll
        for (int p = 0; p < 4; p++) {
            int m  = p * 32 + arl;
            int gm = bm + m;
            int gk = k0 + ak4 * 4;
            float4 v = make_float4(0.f, 0.f, 0.f, 0.f);
            if (gm < M && gk < K)
                v = *reinterpret_cast<const float4*>(g_agg + (size_t)gm * K + gk);
            float4 h, l;
            split_tf32(v.x, h.x, l.x);
            split_tf32(v.y, h.y, l.y);
            split_tf32(v.z, h.z, l.z);
            split_tf32(v.w, h.w, l.w);
            *reinterpret_cast<float4*>(As_h + m * AS_STRIDE + ak4 * 4) = h;
            *reinterpret_cast<float4*>(As_l + m * AS_STRIDE + ak4 * 4) = l;
        }
        // ---- load B tile [32 x 64]
        #pragma unroll
        for (int p = 0; p < 2; p++) {
            int kr = p * 16 + bkr;
            int gk = k0 + kr;
            int gn = bn + bn4 * 4;
            float4 v = make_float4(0.f, 0.f, 0.f, 0.f);
            if (gk < K && gn < N)
                v = *reinterpret_cast<const float4*>(W + (size_t)gk * N + gn);
            float4 h, l;
            split_tf32(v.x, h.x, l.x);
            split_tf32(v.y, h.y, l.y);
            split_tf32(v.z, h.z, l.z);
            split_tf32(v.w, h.w, l.w);
            *reinterpret_cast<float4*>(Bs_h + kr * BS_STRIDE + bn4 * 4) = h;
            *reinterpret_cast<float4*>(Bs_l + kr * BS_STRIDE + bn4 * 4) = l;
        }
        __syncthreads();

        #pragma unroll
        for (int kk = 0; kk < 4; kk++) {
            uint32_t ah[2][4], al[2][4], bh[4][2], bl[4][2];
            #pragma unroll
            for (int mt = 0; mt < 2; mt++) {
                int row = wm + mt * 16 + r;
                const float* ph = As_h + row * AS_STRIDE + kk * 8 + c;
                const float* pl = As_l + row * AS_STRIDE + kk * 8 + c;
                ah[mt][0] = __float_as_uint(ph[0]);
                ah[mt][1] = __float_as_uint(ph[8 * AS_STRIDE]);
                ah[mt][2] = __float_as_uint(ph[4]);
                ah[mt][3] = __float_as_uint(ph[8 * AS_STRIDE + 4]);
                al[mt][0] = __float_as_uint(pl[0]);
                al[mt][1] = __float_as_uint(pl[8 * AS_STRIDE]);
                al[mt][2] = __float_as_uint(pl[4]);
                al[mt][3] = __float_as_uint(pl[8 * AS_STRIDE + 4]);
            }
            #pragma unroll
            for (int nt = 0; nt < 4; nt++) {
                int col = wn + nt * 8 + r;
                const float* qh = Bs_h + (kk * 8 + c) * BS_STRIDE + col;
                const float* ql = Bs_l + (kk * 8 + c) * BS_STRIDE + col;
                bh[nt][0] = __float_as_uint(qh[0]);
                bh[nt][1] = __float_as_uint(qh[4 * BS_STRIDE]);
                bl[nt][0] = __float_as_uint(ql[0]);
                bl[nt][1] = __float_as_uint(ql[4 * BS_STRIDE]);
            }
            #pragma unroll
            for (int mt = 0; mt < 2; mt++)
                #pragma unroll
                for (int nt = 0; nt < 4; nt++) {
                    mma8(acc[mt][nt], ah[mt], bh[nt]);   // hi*hi
                    mma8(acc[mt][nt], al[mt], bh[nt]);   // lo*hi
                    mma8(acc[mt][nt], ah[mt], bl[nt]);   // hi*lo
                }
        }
        __syncthreads();
    }

    // ---- epilogue: bias + leaky relu, float2 stores (8B aligned: N even, gn even)
    #pragma unroll
    for (int mt = 0; mt < 2; mt++) {
        int gm0 = bm + wm + mt * 16 + r;
        #pragma unroll
        for (int nt = 0; nt < 4; nt++) {
            int gn = bn + wn + nt * 8 + 2 * c;
            if (gn >= N) continue;
            float b0 = bias[gn], b1 = bias[gn + 1];
            float v0 = acc[mt][nt][0] + b0;
            float v1 = acc[mt][nt][1] + b1;
            float v2 = acc[mt][nt][2] + b0;
            float v3 = acc[mt][nt][3] + b1;
            v0 = v0 > 0.f ? v0 : NEG_SLOPE * v0;
            v1 = v1 > 0.f ? v1 : NEG_SLOPE * v1;
            v2 = v2 > 0.f ? v2 : NEG_SLOPE * v2;
            v3 = v3 > 0.f ? v3 : NEG_SLOPE * v3;
            if (gm0 < M)
                *reinterpret_cast<float2*>(out + (size_t)gm0 * N + gn) = make_float2(v0, v1);
            if (gm0 + 8 < M)
                *reinterpret_cast<float2*>(out + (size_t)(gm0 + 8) * N + gn) = make_float2(v2, v3);
        }
    }
}

// ---------------------------------------------------------------------------
// g_z = lrelu(g_h2[vcat] @ W3 + b3)  [M=2*N_PAIRS, K=D_FEAT, N=D_OUT]
#define BM 64
#define BN 64
#define BK 16
__global__ __launch_bounds__(256) void gemm_pairs_kernel(
        const int* __restrict__ v1, const int* __restrict__ v2,
        const float* __restrict__ W, const float* __restrict__ bias) {
    const int K = D_FEAT, N = D_OUT;

    __shared__ __align__(16) float As[BK][BM];
    __shared__ __align__(16) float Bs[BK][BN];
    __shared__ int rows[BM];

    int bm = blockIdx.y * BM;
    int bn = blockIdx.x * BN;
    int tid = threadIdx.x;
    int tx = tid & 15, ty = tid >> 4;

    if (tid < BM) {
        int gm = bm + tid;
        rows[tid] = (gm < N_PAIRS) ? v1[gm] : v2[gm - N_PAIRS];
    }
    __syncthreads();

    int a_row = tid >> 2;
    int a_k4  = (tid & 3) * 4;
    int b_row = tid >> 4;
    int b_c4  = (tid & 15) * 4;

    float acc[4][4] = {};

    for (int k0 = 0; k0 < K; k0 += BK) {
        {
            int node = rows[a_row];
            int gk = k0 + a_k4;
            float4 v = make_float4(0.f, 0.f, 0.f, 0.f);
            if (gk + 3 < K) {
                v = *reinterpret_cast<const float4*>(g_h2 + (size_t)node * K + gk);
            } else {
                #pragma unroll
                for (int j = 0; j < 4; j++) {
                    int kk = gk + j;
                    reinterpret_cast<float*>(&v)[j] = (kk < K) ? g_h2[(size_t)node * K + kk] : 0.f;
                }
            }
            As[a_k4 + 0][a_row] = v.x;
            As[a_k4 + 1][a_row] = v.y;
            As[a_k4 + 2][a_row] = v.z;
            As[a_k4 + 3][a_row] = v.w;
        }
        {
            int gk = k0 + b_row;
            int gn = bn + b_c4;
            float4 v = make_float4(0.f, 0.f, 0.f, 0.f);
            if (gk < K) {
                const float* wrow = W + (size_t)gk * N;
                if (gn + 3 < N) {
                    float2 lo = *reinterpret_cast<const float2*>(wrow + gn);
                    float2 hi = *reinterpret_cast<const float2*>(wrow + gn + 2);
                    v = make_float4(lo.x, lo.y, hi.x, hi.y);
                } else {
                    #pragma unroll
                    for (int j = 0; j < 4; j++) {
                        int nn = gn + j;
                        reinterpret_cast<float*>(&v)[j] = (nn < N) ? wrow[nn] : 0.f;
                    }
                }
            }
            *reinterpret_cast<float4*>(&Bs[b_row][b_c4]) = v;
        }
        __syncthreads();

        #pragma unroll
        for (int k = 0; k < BK; k++) {
            float4 a4 = *reinterpret_cast<const float4*>(&As[k][ty * 4]);
            float4 b4 = *reinterpret_cast<const float4*>(&Bs[k][tx * 4]);
            float a[4] = {a4.x, a4.y, a4.z, a4.w};
            float bb[4] = {b4.x, b4.y, b4.z, b4.w};
            #pragma unroll
            for (int i = 0; i < 4; i++)
                #pragma unroll
                for (int j = 0; j < 4; j++)
                    acc[i][j] += a[i] * bb[j];
        }
        __syncthreads();
    }

    #pragma unroll
    for (int i = 0; i < 4; i++) {
        int gm = bm + ty * 4 + i;
        #pragma unroll
        for (int j = 0; j < 4; j++) {
            int gn = bn + tx * 4 + j;
            if (gn >= N) continue;
            float cc = acc[i][j] + bias[gn];
            g_z[(size_t)gm * N + gn] = cc > 0.f ? cc : NEG_SLOPE * cc;
        }
    }
}

// ---------------------------------------------------------------------------
// L2 normalize each row of g_z -> out, one warp per row
__global__ void normalize_kernel(float* __restrict__ out) {
    int row  = (blockIdx.x * blockDim.x + threadIdx.x) >> 5;
    int lane = threadIdx.x & 31;
    if (row >= 2 * N_PAIRS) return;
    const float* zr = g_z + (size_t)row * D_OUT;
    float ss = 0.f;
    for (int i = lane; i < D_OUT; i += 32) { float v = zr[i]; ss += v * v; }
    #pragma unroll
    for (int o = 16; o; o >>= 1) ss += __shfl_xor_sync(0xFFFFFFFFu, ss, o);
    float norm = sqrtf(ss);
    float inv = 1.f / fmaxf(norm, 1e-12f);
    for (int i = lane; i < D_OUT; i += 32) out[(size_t)row * D_OUT + i] = zr[i] * inv;
}

// ---------------------------------------------------------------------------
extern "C" void kernel_launch(void* const* d_in, const int* in_sizes, int n_in,
                              void* d_out, int out_size) {
    const float* features = (const float*)d_in[0];
    const int*   src      = (const int*)  d_in[1];
    const int*   dst      = (const int*)  d_in[2];
    const int*   v1       = (const int*)  d_in[3];
    const int*   v2       = (const int*)  d_in[4];
    const float* W1       = (const float*)d_in[5];
    const float* b1       = (const float*)d_in[6];
    const float* W2       = (const float*)d_in[7];
    const float* b2       = (const float*)d_in[8];
    const float* W3       = (const float*)d_in[9];
    const float* b3       = (const float*)d_in[10];
    float* out = (float*)d_out;
    (void)in_sizes; (void)n_in; (void)out_size;

    const size_t n4 = (size_t)N_NODES * D_FEAT / 4;
    int copy_blocks = (int)((n4 + 255) / 256);
    int scat_blocks = (N_EDGES * 32 + 255) / 256;

    size_t tc_smem = SMEM_FLOATS * sizeof(float);  // 55296 B > 48K default
    cudaFuncSetAttribute(gemm_nodes_tc, cudaFuncAttributeMaxDynamicSharedMemorySize,
                         (int)tc_smem);

    dim3 tc_grid((D_FEAT + TC_BN - 1) / TC_BN, (N_NODES + TC_BM - 1) / TC_BM);
    dim3 gemm_pairs_grid((D_OUT + BN - 1) / BN, (2 * N_PAIRS) / BM);

    // layer 1: g_agg = features; g_agg += scatter; h1 = lrelu(g_agg @ W1 + b1)
    copy_to_agg_kernel<<<copy_blocks, 256>>>(features, 1);
    scatter_kernel<<<scat_blocks, 256>>>(features, src, dst, 0);
    gemm_nodes_tc<<<tc_grid, 256, tc_smem>>>(W1, b1, /*out_sel=*/0);

    // layer 2: g_agg = h1; g_agg += scatter; h2 = lrelu(g_agg @ W2 + b2)
    copy_to_agg_kernel<<<copy_blocks, 256>>>(nullptr, 0);
    scatter_kernel<<<scat_blocks, 256>>>(features, src, dst, 1);
    gemm_nodes_tc<<<tc_grid, 256, tc_smem>>>(W2, b2, /*out_sel=*/1);

    // pair projection + normalize
    gemm_pairs_kernel<<<gemm_pairs_grid, 256>>>(v1, v2, W3, b3);
    normalize_kernel<<<(2 * N_PAIRS * 32 + 255) / 256, 256>>>(out);
}

// round 5
// speedup vs baseline: 1.6038x; 1.2093x over previous
#include <cuda_runtime.h>
#include <math.h>
#include <stdint.h>

#define N_NODES 50000
#define D_FEAT  364
#define D_OUT   150
#define N_PAIRS 8192
#define N_EDGES 200000
#define NEG_SLOPE 0.01f

// Scratch (no cudaMalloc allowed). 16B-aligned for float4.
__device__ __align__(16) float g_agg[(size_t)N_NODES * D_FEAT];
__device__ __align__(16) float g_h1 [(size_t)N_NODES * D_FEAT];
__device__ __align__(16) float g_h2 [(size_t)N_NODES * D_FEAT];
__device__ __align__(16) float g_z  [(size_t)2 * N_PAIRS * D_OUT];

// ---------------------------------------------------------------------------
// g_agg = x  (residual folded into aggregation buffer)
__global__ void copy_to_agg_kernel(const float* __restrict__ x_ext, int use_ext) {
    size_t n4 = (size_t)N_NODES * D_FEAT / 4;
    size_t i = (size_t)blockIdx.x * blockDim.x + threadIdx.x;
    if (i >= n4) return;
    const float4* s = use_ext ? reinterpret_cast<const float4*>(x_ext)
                              : reinterpret_cast<const float4*>(g_h1);
    reinterpret_cast<float4*>(g_agg)[i] = s[i];
}

// ---------------------------------------------------------------------------
// scatter: g_agg[dst] += x[src], one warp per edge, vectorized RED (sm_90+)
__global__ void scatter_kernel(const float* __restrict__ x_ext,
                               const int* __restrict__ src,
                               const int* __restrict__ dst,
                               int layer) {
    int warp = (blockIdx.x * blockDim.x + threadIdx.x) >> 5;
    int lane = threadIdx.x & 31;
    if (warp >= N_EDGES) return;
    const float* __restrict__ x = (layer == 0) ? x_ext : g_h1;
    int s = src[warp];
    int d = dst[warp];
    const float4* xs = reinterpret_cast<const float4*>(x + (size_t)s * D_FEAT);
    float* ad = g_agg + (size_t)d * D_FEAT;
    #pragma unroll
    for (int i = lane; i < D_FEAT / 4; i += 32) {   // 91 float4 -> 3 iters
        float4 v = xs[i];
        asm volatile("red.global.add.v4.f32 [%0], {%1,%2,%3,%4};"
                     :: "l"(ad + i * 4), "f"(v.x), "f"(v.y), "f"(v.z), "f"(v.w)
                     : "memory");
    }
}

// ---------------------------------------------------------------------------
// tf32 helpers
__device__ __forceinline__ uint32_t f2tf32(float x) {
    uint32_t r;
    asm("cvt.rna.tf32.f32 %0, %1;" : "=r"(r) : "f"(x));
    return r;
}
__device__ __forceinline__ void split_tf32(float v, float& h, float& l) {
    h = __uint_as_float(f2tf32(v));
    l = __uint_as_float(f2tf32(v - h));
}
__device__ __forceinline__ void mma8(float d[4], const uint32_t a[4], const uint32_t b[2]) {
    asm volatile(
        "mma.sync.aligned.m16n8k8.row.col.f32.tf32.tf32.f32 "
        "{%0,%1,%2,%3}, {%4,%5,%6,%7}, {%8,%9}, {%0,%1,%2,%3};\n"
        : "+f"(d[0]), "+f"(d[1]), "+f"(d[2]), "+f"(d[3])
        : "r"(a[0]), "r"(a[1]), "r"(a[2]), "r"(a[3]), "r"(b[0]), "r"(b[1]));
}

// ---------------------------------------------------------------------------
// out = lrelu(g_agg @ W + b) using 3xTF32 tensor-core GEMM.
// Tile: BM=128, BN=128, BK=32. 256 threads = 8 warps as 2(m) x 4(n),
// warp tile 64x32 (mt=4 x nt=4).
#define TC_BM 128
#define TC_BN 128
#define TC_BK 32
#define AS_STRIDE 36    // == 4 mod 32 -> A frag banks 4r+c, conflict-free
#define BS_STRIDE 136   // == 8 mod 32 -> B frag banks 8c+r, conflict-free
#define SMEM_FLOATS (2 * TC_BM * AS_STRIDE + 2 * TC_BK * BS_STRIDE)  // 17920

__global__ __launch_bounds__(256) void gemm_nodes_tc(
        const float* __restrict__ W, const float* __restrict__ bias, int out_sel) {
    const int M = N_NODES, K = D_FEAT, N = D_FEAT;
    float* __restrict__ out = out_sel ? g_h2 : g_h1;

    extern __shared__ float smf[];
    float* As_h = smf;                                 // [128][36]
    float* As_l = smf + TC_BM * AS_STRIDE;
    float* Bs_h = smf + 2 * TC_BM * AS_STRIDE;         // [32][136]
    float* Bs_l = Bs_h + TC_BK * BS_STRIDE;

    int bm = blockIdx.y * TC_BM;
    int bn = blockIdx.x * TC_BN;
    int tid = threadIdx.x;
    int lane = tid & 31;
    int wid = tid >> 5;
    int wm = (wid & 1) * 64;    // 2 warps along m
    int wn = (wid >> 1) * 32;   // 4 warps along n
    int r = lane >> 2;          // 0..7
    int c = lane & 3;           // 0..3

    float acc[4][4][4];
    #pragma unroll
    for (int i = 0; i < 4; i++)
        #pragma unroll
        for (int j = 0; j < 4; j++)
            #pragma unroll
            for (int q = 0; q < 4; q++) acc[i][j][q] = 0.f;

    int ak4 = tid & 7;      // float4 index along k (A)
    int arl = tid >> 3;     // 0..31 row (A)
    int bn4 = tid & 31;     // float4 index along n (B)
    int bkr = tid >> 5;     // 0..7 k row (B)

    for (int k0 = 0; k0 < K; k0 += TC_BK) {
        // ---- A tile [128 x 32], split hi/lo
        #pragma unroll
        for (int p = 0; p < 4; p++) {
            int m  = p * 32 + arl;
            int gm = bm + m;
            int gk = k0 + ak4 * 4;
            float4 v = make_float4(0.f, 0.f, 0.f, 0.f);
            if (gm < M && gk < K)
                v = *reinterpret_cast<const float4*>(g_agg + (size_t)gm * K + gk);
            float4 h, l;
            split_tf32(v.x, h.x, l.x);
            split_tf32(v.y, h.y, l.y);
            split_tf32(v.z, h.z, l.z);
            split_tf32(v.w, h.w, l.w);
            *reinterpret_cast<float4*>(As_h + m * AS_STRIDE + ak4 * 4) = h;
            *reinterpret_cast<float4*>(As_l + m * AS_STRIDE + ak4 * 4) = l;
        }
        // ---- B tile [32 x 128], split hi/lo
        #pragma unroll
        for (int p = 0; p < 4; p++) {
            int kr = p * 8 + bkr;
            int gk = k0 + kr;
            int gn = bn + bn4 * 4;
            float4 v = make_float4(0.f, 0.f, 0.f, 0.f);
            if (gk < K && gn < N)
                v = *reinterpret_cast<const float4*>(W + (size_t)gk * N + gn);
            float4 h, l;
            split_tf32(v.x, h.x, l.x);
            split_tf32(v.y, h.y, l.y);
            split_tf32(v.z, h.z, l.z);
            split_tf32(v.w, h.w, l.w);
            *reinterpret_cast<float4*>(Bs_h + kr * BS_STRIDE + bn4 * 4) = h;
            *reinterpret_cast<float4*>(Bs_l + kr * BS_STRIDE + bn4 * 4) = l;
        }
        __syncthreads();

        #pragma unroll
        for (int kk = 0; kk < 4; kk++) {
            uint32_t ah[4][4], al[4][4], bh[4][2], bl[4][2];
            #pragma unroll
            for (int mt = 0; mt < 4; mt++) {
                int row = wm + mt * 16 + r;
                const float* ph = As_h + row * AS_STRIDE + kk * 8 + c;
                const float* pl = As_l + row * AS_STRIDE + kk * 8 + c;
                ah[mt][0] = __float_as_uint(ph[0]);
                ah[mt][1] = __float_as_uint(ph[8 * AS_STRIDE]);
                ah[mt][2] = __float_as_uint(ph[4]);
                ah[mt][3] = __float_as_uint(ph[8 * AS_STRIDE + 4]);
                al[mt][0] = __float_as_uint(pl[0]);
                al[mt][1] = __float_as_uint(pl[8 * AS_STRIDE]);
                al[mt][2] = __float_as_uint(pl[4]);
                al[mt][3] = __float_as_uint(pl[8 * AS_STRIDE + 4]);
            }
            #pragma unroll
            for (int nt = 0; nt < 4; nt++) {
                int col = wn + nt * 8 + r;
                const float* qh = Bs_h + (kk * 8 + c) * BS_STRIDE + col;
                const float* ql = Bs_l + (kk * 8 + c) * BS_STRIDE + col;
                bh[nt][0] = __float_as_uint(qh[0]);
                bh[nt][1] = __float_as_uint(qh[4 * BS_STRIDE]);
                bl[nt][0] = __float_as_uint(ql[0]);
                bl[nt][1] = __float_as_uint(ql[4 * BS_STRIDE]);
            }
            #pragma unroll
            for (int mt = 0; mt < 4; mt++)
                #pragma unroll
                for (int nt = 0; nt < 4; nt++) {
                    mma8(acc[mt][nt], ah[mt], bh[nt]);   // hi*hi
                    mma8(acc[mt][nt], al[mt], bh[nt]);   // lo*hi
                    mma8(acc[mt][nt], ah[mt], bl[nt]);   // hi*lo
                }
        }
        __syncthreads();
    }

    // ---- epilogue: bias + leaky relu, float2 stores (8B aligned: gn even)
    #pragma unroll
    for (int mt = 0; mt < 4; mt++) {
        int gm0 = bm + wm + mt * 16 + r;
        #pragma unroll
        for (int nt = 0; nt < 4; nt++) {
            int gn = bn + wn + nt * 8 + 2 * c;
            if (gn >= N) continue;
            float b0 = bias[gn], b1 = bias[gn + 1];
            float v0 = acc[mt][nt][0] + b0;
            float v1 = acc[mt][nt][1] + b1;
            float v2 = acc[mt][nt][2] + b0;
            float v3 = acc[mt][nt][3] + b1;
            v0 = v0 > 0.f ? v0 : NEG_SLOPE * v0;
            v1 = v1 > 0.f ? v1 : NEG_SLOPE * v1;
            v2 = v2 > 0.f ? v2 : NEG_SLOPE * v2;
            v3 = v3 > 0.f ? v3 : NEG_SLOPE * v3;
            if (gm0 < M)
                *reinterpret_cast<float2*>(out + (size_t)gm0 * N + gn) = make_float2(v0, v1);
            if (gm0 + 8 < M)
                *reinterpret_cast<float2*>(out + (size_t)(gm0 + 8) * N + gn) = make_float2(v2, v3);
        }
    }
}

// ---------------------------------------------------------------------------
// g_z = lrelu(g_h2[vcat] @ W3 + b3)  [M=2*N_PAIRS, K=D_FEAT, N=D_OUT]
#define BM 64
#define BN 64
#define BK 16
__global__ __launch_bounds__(256) void gemm_pairs_kernel(
        const int* __restrict__ v1, const int* __restrict__ v2,
        const float* __restrict__ W, const float* __restrict__ bias) {
    const int K = D_FEAT, N = D_OUT;

    __shared__ __align__(16) float As[BK][BM];
    __shared__ __align__(16) float Bs[BK][BN];
    __shared__ int rows[BM];

    int bm = blockIdx.y * BM;
    int bn = blockIdx.x * BN;
    int tid = threadIdx.x;
    int tx = tid & 15, ty = tid >> 4;

    if (tid < BM) {
        int gm = bm + tid;
        rows[tid] = (gm < N_PAIRS) ? v1[gm] : v2[gm - N_PAIRS];
    }
    __syncthreads();

    int a_row = tid >> 2;
    int a_k4  = (tid & 3) * 4;
    int b_row = tid >> 4;
    int b_c4  = (tid & 15) * 4;

    float acc[4][4] = {};

    for (int k0 = 0; k0 < K; k0 += BK) {
        {
            int node = rows[a_row];
            int gk = k0 + a_k4;
            float4 v = make_float4(0.f, 0.f, 0.f, 0.f);
            if (gk + 3 < K) {
                v = *reinterpret_cast<const float4*>(g_h2 + (size_t)node * K + gk);
            } else {
                #pragma unroll
                for (int j = 0; j < 4; j++) {
                    int kk = gk + j;
                    reinterpret_cast<float*>(&v)[j] = (kk < K) ? g_h2[(size_t)node * K + kk] : 0.f;
                }
            }
            As[a_k4 + 0][a_row] = v.x;
            As[a_k4 + 1][a_row] = v.y;
            As[a_k4 + 2][a_row] = v.z;
            As[a_k4 + 3][a_row] = v.w;
        }
        {
            int gk = k0 + b_row;
            int gn = bn + b_c4;
            float4 v = make_float4(0.f, 0.f, 0.f, 0.f);
            if (gk < K) {
                const float* wrow = W + (size_t)gk * N;
                if (gn + 3 < N) {
                    float2 lo = *reinterpret_cast<const float2*>(wrow + gn);
                    float2 hi = *reinterpret_cast<const float2*>(wrow + gn + 2);
                    v = make_float4(lo.x, lo.y, hi.x, hi.y);
                } else {
                    #pragma unroll
                    for (int j = 0; j < 4; j++) {
                        int nn = gn + j;
                        reinterpret_cast<float*>(&v)[j] = (nn < N) ? wrow[nn] : 0.f;
                    }
                }
            }
            *reinterpret_cast<float4*>(&Bs[b_row][b_c4]) = v;
        }
        __syncthreads();

        #pragma unroll
        for (int k = 0; k < BK; k++) {
            float4 a4 = *reinterpret_cast<const float4*>(&As[k][ty * 4]);
            float4 b4 = *reinterpret_cast<const float4*>(&Bs[k][tx * 4]);
            float a[4] = {a4.x, a4.y, a4.z, a4.w};
            float bb[4] = {b4.x, b4.y, b4.z, b4.w};
            #pragma unroll
            for (int i = 0; i < 4; i++)
                #pragma unroll
                for (int j = 0; j < 4; j++)
                    acc[i][j] += a[i] * bb[j];
        }
        __syncthreads();
    }

    #pragma unroll
    for (int i = 0; i < 4; i++) {
        int gm = bm + ty * 4 + i;
        #pragma unroll
        for (int j = 0; j < 4; j++) {
            int gn = bn + tx * 4 + j;
            if (gn >= N) continue;
            float cc = acc[i][j] + bias[gn];
            g_z[(size_t)gm * N + gn] = cc > 0.f ? cc : NEG_SLOPE * cc;
        }
    }
}

// ---------------------------------------------------------------------------
// L2 normalize each row of g_z -> out, one warp per row
__global__ void normalize_kernel(float* __restrict__ out) {
    int row  = (blockIdx.x * blockDim.x + threadIdx.x) >> 5;
    int lane = threadIdx.x & 31;
    if (row >= 2 * N_PAIRS) return;
    const float* zr = g_z + (size_t)row * D_OUT;
    float ss = 0.f;
    for (int i = lane; i < D_OUT; i += 32) { float v = zr[i]; ss += v * v; }
    #pragma unroll
    for (int o = 16; o; o >>= 1) ss += __shfl_xor_sync(0xFFFFFFFFu, ss, o);
    float norm = sqrtf(ss);
    float inv = 1.f / fmaxf(norm, 1e-12f);
    for (int i = lane; i < D_OUT; i += 32) out[(size_t)row * D_OUT + i] = zr[i] * inv;
}

// ---------------------------------------------------------------------------
extern "C" void kernel_launch(void* const* d_in, const int* in_sizes, int n_in,
                              void* d_out, int out_size) {
    const float* features = (const float*)d_in[0];
    const int*   src      = (const int*)  d_in[1];
    const int*   dst      = (const int*)  d_in[2];
    const int*   v1       = (const int*)  d_in[3];
    const int*   v2       = (const int*)  d_in[4];
    const float* W1       = (const float*)d_in[5];
    const float* b1       = (const float*)d_in[6];
    const float* W2       = (const float*)d_in[7];
    const float* b2       = (const float*)d_in[8];
    const float* W3       = (const float*)d_in[9];
    const float* b3       = (const float*)d_in[10];
    float* out = (float*)d_out;
    (void)in_sizes; (void)n_in; (void)out_size;

    const size_t n4 = (size_t)N_NODES * D_FEAT / 4;
    int copy_blocks = (int)((n4 + 255) / 256);
    int scat_blocks = (N_EDGES * 32 + 255) / 256;

    size_t tc_smem = SMEM_FLOATS * sizeof(float);  // 71680 B
    cudaFuncSetAttribute(gemm_nodes_tc, cudaFuncAttributeMaxDynamicSharedMemorySize,
                         (int)tc_smem);

    dim3 tc_grid((D_FEAT + TC_BN - 1) / TC_BN, (N_NODES + TC_BM - 1) / TC_BM);
    dim3 gemm_pairs_grid((D_OUT + BN - 1) / BN, (2 * N_PAIRS) / BM);

    // layer 1
    copy_to_agg_kernel<<<copy_blocks, 256>>>(features, 1);
    scatter_kernel<<<scat_blocks, 256>>>(features, src, dst, 0);
    gemm_nodes_tc<<<tc_grid, 256, tc_smem>>>(W1, b1, /*out_sel=*/0);

    // layer 2
    copy_to_agg_kernel<<<copy_blocks, 256>>>(nullptr, 0);
    scatter_kernel<<<scat_blocks, 256>>>(features, src, dst, 1);
    gemm_nodes_tc<<<tc_grid, 256, tc_smem>>>(W2, b2, /*out_sel=*/1);

    // pair projection + normalize
    gemm_pairs_kernel<<<gemm_pairs_grid, 256>>>(v1, v2, W3, b3);
    normalize_kernel<<<(2 * N_PAIRS * 32 + 255) / 256, 256>>>(out);
}

// round 7
// speedup vs baseline: 1.7233x; 1.0745x over previous
#include <cuda_runtime.h>
#include <math.h>
#include <stdint.h>

#define N_NODES 50000
#define D_FEAT  364
#define D_OUT   150
#define N_PAIRS 8192
#define N_EDGES 200000
#define NEG_SLOPE 0.01f

// Scratch (no cudaMalloc allowed). 16B-aligned for float4.
__device__ __align__(16) float g_agg[(size_t)N_NODES * D_FEAT];
__device__ __align__(16) float g_h1 [(size_t)N_NODES * D_FEAT];
__device__ __align__(16) float g_h2 [(size_t)N_NODES * D_FEAT];
__device__ __align__(16) float g_z  [(size_t)2 * N_PAIRS * D_OUT];

// ---------------------------------------------------------------------------
// g_agg = x (residual base). Separate kernel => grid-wide barrier, no race.
__global__ void copy_to_agg_kernel(const float* __restrict__ x_ext, int use_ext) {
    size_t n4 = (size_t)N_NODES * D_FEAT / 4;
    size_t i = (size_t)blockIdx.x * blockDim.x + threadIdx.x;
    if (i >= n4) return;
    const float4* s = use_ext ? reinterpret_cast<const float4*>(x_ext)
                              : reinterpret_cast<const float4*>(g_h1);
    reinterpret_cast<float4*>(g_agg)[i] = s[i];
}

// ---------------------------------------------------------------------------
// scatter: g_agg[dst] += x[src], one warp per edge, vectorized RED (sm_90+)
__global__ void scatter_kernel(const float* __restrict__ x_ext,
                               const int* __restrict__ src,
                               const int* __restrict__ dst,
                               int layer) {
    int warp = (blockIdx.x * blockDim.x + threadIdx.x) >> 5;
    int lane = threadIdx.x & 31;
    if (warp >= N_EDGES) return;
    const float* __restrict__ x = (layer == 0) ? x_ext : g_h1;
    int s = src[warp];
    int d = dst[warp];
    const float4* xs = reinterpret_cast<const float4*>(x + (size_t)s * D_FEAT);
    float* ad = g_agg + (size_t)d * D_FEAT;
    #pragma unroll
    for (int i = lane; i < D_FEAT / 4; i += 32) {   // 91 float4 -> 3 iters
        float4 v = xs[i];
        asm volatile("red.global.add.v4.f32 [%0], {%1,%2,%3,%4};"
                     :: "l"(ad + i * 4), "f"(v.x), "f"(v.y), "f"(v.z), "f"(v.w)
                     : "memory");
    }
}

// ---------------------------------------------------------------------------
// tf32 helpers
__device__ __forceinline__ uint32_t f2tf32(float x) {
    uint32_t r;
    asm("cvt.rna.tf32.f32 %0, %1;" : "=r"(r) : "f"(x));
    return r;
}
__device__ __forceinline__ void split_tf32(float v, float& h, float& l) {
    h = __uint_as_float(f2tf32(v));
    l = __uint_as_float(f2tf32(v - h));
}
__device__ __forceinline__ void mma8(float d[4], const uint32_t a[4], const uint32_t b[2]) {
    asm volatile(
        "mma.sync.aligned.m16n8k8.row.col.f32.tf32.tf32.f32 "
        "{%0,%1,%2,%3}, {%4,%5,%6,%7}, {%8,%9}, {%0,%1,%2,%3};\n"
        : "+f"(d[0]), "+f"(d[1]), "+f"(d[2]), "+f"(d[3])
        : "r"(a[0]), "r"(a[1]), "r"(a[2]), "r"(a[3]), "r"(b[0]), "r"(b[1]));
}

// ---------------------------------------------------------------------------
// out = lrelu(g_agg @ W + b) via 3xTF32 tensor-core GEMM, software pipelined
// with double-buffered smem. Tile BM=128, BN=128, BK=32; 8 warps (2m x 4n),
// warp tile 64x32.
#define TC_BM 128
#define TC_BN 128
#define TC_BK 32
#define AS_STRIDE 36    // == 4 mod 32 -> A frag banks conflict-free
#define BS_STRIDE 136   // == 8 mod 32 -> B frag banks conflict-free
#define A_FLOATS (TC_BM * AS_STRIDE)                     // 4608
#define B_FLOATS (TC_BK * BS_STRIDE)                     // 4352
#define STAGE_FLOATS (2 * A_FLOATS + 2 * B_FLOATS)       // 17920
#define NUM_KTILES ((D_FEAT + TC_BK - 1) / TC_BK)        // 12

__global__ __launch_bounds__(256) void gemm_nodes_tc(
        const float* __restrict__ W, const float* __restrict__ bias, int out_sel) {
    const int M = N_NODES, K = D_FEAT, N = D_FEAT;
    float* __restrict__ out = out_sel ? g_h2 : g_h1;

    extern __shared__ float smf[];   // 2 stages x STAGE_FLOATS

    int bm = blockIdx.y * TC_BM;
    int bn = blockIdx.x * TC_BN;
    int tid = threadIdx.x;
    int lane = tid & 31;
    int wid = tid >> 5;
    int wm = (wid & 1) * 64;
    int wn = (wid >> 1) * 32;
    int r = lane >> 2;
    int c = lane & 3;

    float acc[4][4][4];
    #pragma unroll
    for (int i = 0; i < 4; i++)
        #pragma unroll
        for (int j = 0; j < 4; j++)
            #pragma unroll
            for (int q = 0; q < 4; q++) acc[i][j][q] = 0.f;

    int ak4 = tid & 7;      // float4 index along k (A)
    int arl = tid >> 3;     // 0..31 row (A)
    int bn4 = tid & 31;     // float4 index along n (B)
    int bkr = tid >> 5;     // 0..7 k row (B)

    float4 a_pf[4], b_pf[4];

    // -- prologue: load tile 0
    {
        int gk = ak4 * 4;
        #pragma unroll
        for (int p = 0; p < 4; p++) {
            int gm = bm + p * 32 + arl;
            a_pf[p] = (gm < M && gk < K)
                ? *reinterpret_cast<const float4*>(g_agg + (size_t)gm * K + gk)
                : make_float4(0.f, 0.f, 0.f, 0.f);
        }
        int gn = bn + bn4 * 4;
        #pragma unroll
        for (int p = 0; p < 4; p++) {
            int gkb = p * 8 + bkr;
            b_pf[p] = (gkb < K && gn < N)
                ? *reinterpret_cast<const float4*>(W + (size_t)gkb * N + gn)
                : make_float4(0.f, 0.f, 0.f, 0.f);
        }
    }
    // split + store stage 0
    {
        float* As_h = smf;
        float* As_l = smf + A_FLOATS;
        float* Bs_h = smf + 2 * A_FLOATS;
        float* Bs_l = Bs_h + B_FLOATS;
        #pragma unroll
        for (int p = 0; p < 4; p++) {
            int m = p * 32 + arl;
            float4 h, l;
            split_tf32(a_pf[p].x, h.x, l.x);
            split_tf32(a_pf[p].y, h.y, l.y);
            split_tf32(a_pf[p].z, h.z, l.z);
            split_tf32(a_pf[p].w, h.w, l.w);
            *reinterpret_cast<float4*>(As_h + m * AS_STRIDE + ak4 * 4) = h;
            *reinterpret_cast<float4*>(As_l + m * AS_STRIDE + ak4 * 4) = l;
        }
        #pragma unroll
        for (int p = 0; p < 4; p++) {
            int kr = p * 8 + bkr;
            float4 h, l;
            split_tf32(b_pf[p].x, h.x, l.x);
            split_tf32(b_pf[p].y, h.y, l.y);
            split_tf32(b_pf[p].z, h.z, l.z);
            split_tf32(b_pf[p].w, h.w, l.w);
            *reinterpret_cast<float4*>(Bs_h + kr * BS_STRIDE + bn4 * 4) = h;
            *reinterpret_cast<float4*>(Bs_l + kr * BS_STRIDE + bn4 * 4) = l;
        }
    }
    __syncthreads();

    for (int t = 0; t < NUM_KTILES; t++) {
        // -- prefetch next tile into registers (latency hidden by MMAs below)
        if (t + 1 < NUM_KTILES) {
            int k0 = (t + 1) * TC_BK;
            int gk = k0 + ak4 * 4;
            #pragma unroll
            for (int p = 0; p < 4; p++) {
                int gm = bm + p * 32 + arl;
                a_pf[p] = (gm < M && gk < K)
                    ? *reinterpret_cast<const float4*>(g_agg + (size_t)gm * K + gk)
                    : make_float4(0.f, 0.f, 0.f, 0.f);
            }
            int gn = bn + bn4 * 4;
            #pragma unroll
            for (int p = 0; p < 4; p++) {
                int gkb = k0 + p * 8 + bkr;
                b_pf[p] = (gkb < K && gn < N)
                    ? *reinterpret_cast<const float4*>(W + (size_t)gkb * N + gn)
                    : make_float4(0.f, 0.f, 0.f, 0.f);
            }
        }

        // -- MMA over current stage
        {
            const float* base = smf + (t & 1) * STAGE_FLOATS;
            const float* As_h = base;
            const float* As_l = base + A_FLOATS;
            const float* Bs_h = base + 2 * A_FLOATS;
            const float* Bs_l = Bs_h + B_FLOATS;

            #pragma unroll
            for (int kk = 0; kk < 4; kk++) {
                uint32_t ah[4][4], al[4][4], bh[4][2], bl[4][2];
                #pragma unroll
                for (int mt = 0; mt < 4; mt++) {
                    int row = wm + mt * 16 + r;
                    const float* ph = As_h + row * AS_STRIDE + kk * 8 + c;
                    const float* pl = As_l + row * AS_STRIDE + kk * 8 + c;
                    ah[mt][0] = __float_as_uint(ph[0]);
                    ah[mt][1] = __float_as_uint(ph[8 * AS_STRIDE]);
                    ah[mt][2] = __float_as_uint(ph[4]);
                    ah[mt][3] = __float_as_uint(ph[8 * AS_STRIDE + 4]);
                    al[mt][0] = __float_as_uint(pl[0]);
                    al[mt][1] = __float_as_uint(pl[8 * AS_STRIDE]);
                    al[mt][2] = __float_as_uint(pl[4]);
                    al[mt][3] = __float_as_uint(pl[8 * AS_STRIDE + 4]);
                }
                #pragma unroll
                for (int nt = 0; nt < 4; nt++) {
                    int col = wn + nt * 8 + r;
                    const float* qh = Bs_h + (kk * 8 + c) * BS_STRIDE + col;
                    const float* ql = Bs_l + (kk * 8 + c) * BS_STRIDE + col;
                    bh[nt][0] = __float_as_uint(qh[0]);
                    bh[nt][1] = __float_as_uint(qh[4 * BS_STRIDE]);
                    bl[nt][0] = __float_as_uint(ql[0]);
                    bl[nt][1] = __float_as_uint(ql[4 * BS_STRIDE]);
                }
                #pragma unroll
                for (int mt = 0; mt < 4; mt++)
                    #pragma unroll
                    for (int nt = 0; nt < 4; nt++) {
                        mma8(acc[mt][nt], ah[mt], bh[nt]);
                        mma8(acc[mt][nt], al[mt], bh[nt]);
                        mma8(acc[mt][nt], ah[mt], bl[nt]);
                    }
            }
        }

        // -- split + store next tile into other stage
        if (t + 1 < NUM_KTILES) {
            float* base = smf + ((t + 1) & 1) * STAGE_FLOATS;
            float* As_h = base;
            float* As_l = base + A_FLOATS;
            float* Bs_h = base + 2 * A_FLOATS;
            float* Bs_l = Bs_h + B_FLOATS;
            #pragma unroll
            for (int p = 0; p < 4; p++) {
                int m = p * 32 + arl;
                float4 h, l;
                split_tf32(a_pf[p].x, h.x, l.x);
                split_tf32(a_pf[p].y, h.y, l.y);
                split_tf32(a_pf[p].z, h.z, l.z);
                split_tf32(a_pf[p].w, h.w, l.w);
                *reinterpret_cast<float4*>(As_h + m * AS_STRIDE + ak4 * 4) = h;
                *reinterpret_cast<float4*>(As_l + m * AS_STRIDE + ak4 * 4) = l;
            }
            #pragma unroll
            for (int p = 0; p < 4; p++) {
                int kr = p * 8 + bkr;
                float4 h, l;
                split_tf32(b_pf[p].x, h.x, l.x);
                split_tf32(b_pf[p].y, h.y, l.y);
                split_tf32(b_pf[p].z, h.z, l.z);
                split_tf32(b_pf[p].w, h.w, l.w);
                *reinterpret_cast<float4*>(Bs_h + kr * BS_STRIDE + bn4 * 4) = h;
                *reinterpret_cast<float4*>(Bs_l + kr * BS_STRIDE + bn4 * 4) = l;
            }
        }
        __syncthreads();
    }

    // ---- epilogue: bias + leaky relu, float2 stores
    #pragma unroll
    for (int mt = 0; mt < 4; mt++) {
        int gm0 = bm + wm + mt * 16 + r;
        #pragma unroll
        for (int nt = 0; nt < 4; nt++) {
            int gn = bn + wn + nt * 8 + 2 * c;
            if (gn >= N) continue;
            float b0 = bias[gn], b1 = bias[gn + 1];
            float v0 = acc[mt][nt][0] + b0;
            float v1 = acc[mt][nt][1] + b1;
            float v2 = acc[mt][nt][2] + b0;
            float v3 = acc[mt][nt][3] + b1;
            v0 = v0 > 0.f ? v0 : NEG_SLOPE * v0;
            v1 = v1 > 0.f ? v1 : NEG_SLOPE * v1;
            v2 = v2 > 0.f ? v2 : NEG_SLOPE * v2;
            v3 = v3 > 0.f ? v3 : NEG_SLOPE * v3;
            if (gm0 < M)
                *reinterpret_cast<float2*>(out + (size_t)gm0 * N + gn) = make_float2(v0, v1);
            if (gm0 + 8 < M)
                *reinterpret_cast<float2*>(out + (size_t)(gm0 + 8) * N + gn) = make_float2(v2, v3);
        }
    }
}

// ---------------------------------------------------------------------------
// g_z = lrelu(g_h2[vcat] @ W3 + b3)  [M=2*N_PAIRS, K=D_FEAT, N=D_OUT]
#define BM 64
#define BN 64
#define BK 16
__global__ __launch_bounds__(256) void gemm_pairs_kernel(
        const int* __restrict__ v1, const int* __restrict__ v2,
        const float* __restrict__ W, const float* __restrict__ bias) {
    const int K = D_FEAT, N = D_OUT;

    __shared__ __align__(16) float As[BK][BM];
    __shared__ __align__(16) float Bs[BK][BN];
    __shared__ int rows[BM];

    int bm = blockIdx.y * BM;
    int bn = blockIdx.x * BN;
    int tid = threadIdx.x;
    int tx = tid & 15, ty = tid >> 4;

    if (tid < BM) {
        int gm = bm + tid;
        rows[tid] = (gm < N_PAIRS) ? v1[gm] : v2[gm - N_PAIRS];
    }
    __syncthreads();

    int a_row = tid >> 2;
    int a_k4  = (tid & 3) * 4;
    int b_row = tid >> 4;
    int b_c4  = (tid & 15) * 4;

    float acc[4][4] = {};

    for (int k0 = 0; k0 < K; k0 += BK) {
        {
            int node = rows[a_row];
            int gk = k0 + a_k4;
            float4 v = make_float4(0.f, 0.f, 0.f, 0.f);
            if (gk + 3 < K) {
                v = *reinterpret_cast<const float4*>(g_h2 + (size_t)node * K + gk);
            } else {
                #pragma unroll
                for (int j = 0; j < 4; j++) {
                    int kk = gk + j;
                    reinterpret_cast<float*>(&v)[j] = (kk < K) ? g_h2[(size_t)node * K + kk] : 0.f;
                }
            }
            As[a_k4 + 0][a_row] = v.x;
            As[a_k4 + 1][a_row] = v.y;
            As[a_k4 + 2][a_row] = v.z;
            As[a_k4 + 3][a_row] = v.w;
        }
        {
            int gk = k0 + b_row;
            int gn = bn + b_c4;
            float4 v = make_float4(0.f, 0.f, 0.f, 0.f);
            if (gk < K) {
                const float* wrow = W + (size_t)gk * N;
                if (gn + 3 < N) {
                    float2 lo = *reinterpret_cast<const float2*>(wrow + gn);
                    float2 hi = *reinterpret_cast<const float2*>(wrow + gn + 2);
                    v = make_float4(lo.x, lo.y, hi.x, hi.y);
                } else {
                    #pragma unroll
                    for (int j = 0; j < 4; j++) {
                        int nn = gn + j;
                        reinterpret_cast<float*>(&v)[j] = (nn < N) ? wrow[nn] : 0.f;
                    }
                }
            }
            *reinterpret_cast<float4*>(&Bs[b_row][b_c4]) = v;
        }
        __syncthreads();

        #pragma unroll
        for (int k = 0; k < BK; k++) {
            float4 a4 = *reinterpret_cast<const float4*>(&As[k][ty * 4]);
            float4 b4 = *reinterpret_cast<const float4*>(&Bs[k][tx * 4]);
            float a[4] = {a4.x, a4.y, a4.z, a4.w};
            float bb[4] = {b4.x, b4.y, b4.z, b4.w};
            #pragma unroll
            for (int i = 0; i < 4; i++)
                #pragma unroll
                for (int j = 0; j < 4; j++)
                    acc[i][j] += a[i] * bb[j];
        }
        __syncthreads();
    }

    #pragma unroll
    for (int i = 0; i < 4; i++) {
        int gm = bm + ty * 4 + i;
        #pragma unroll
        for (int j = 0; j < 4; j++) {
            int gn = bn + tx * 4 + j;
            if (gn >= N) continue;
            float cc = acc[i][j] + bias[gn];
            g_z[(size_t)gm * N + gn] = cc > 0.f ? cc : NEG_SLOPE * cc;
        }
    }
}

// ---------------------------------------------------------------------------
// L2 normalize each row of g_z -> out, one warp per row
__global__ void normalize_kernel(float* __restrict__ out) {
    int row  = (blockIdx.x * blockDim.x + threadIdx.x) >> 5;
    int lane = threadIdx.x & 31;
    if (row >= 2 * N_PAIRS) return;
    const float* zr = g_z + (size_t)row * D_OUT;
    float ss = 0.f;
    for (int i = lane; i < D_OUT; i += 32) { float v = zr[i]; ss += v * v; }
    #pragma unroll
    for (int o = 16; o; o >>= 1) ss += __shfl_xor_sync(0xFFFFFFFFu, ss, o);
    float norm = sqrtf(ss);
    float inv = 1.f / fmaxf(norm, 1e-12f);
    for (int i = lane; i < D_OUT; i += 32) out[(size_t)row * D_OUT + i] = zr[i] * inv;
}

// ---------------------------------------------------------------------------
extern "C" void kernel_launch(void* const* d_in, const int* in_sizes, int n_in,
                              void* d_out, int out_size) {
    const float* features = (const float*)d_in[0];
    const int*   src      = (const int*)  d_in[1];
    const int*   dst      = (const int*)  d_in[2];
    const int*   v1       = (const int*)  d_in[3];
    const int*   v2       = (const int*)  d_in[4];
    const float* W1       = (const float*)d_in[5];
    const float* b1       = (const float*)d_in[6];
    const float* W2       = (const float*)d_in[7];
    const float* b2       = (const float*)d_in[8];
    const float* W3       = (const float*)d_in[9];
    const float* b3       = (const float*)d_in[10];
    float* out = (float*)d_out;
    (void)in_sizes; (void)n_in; (void)out_size;

    const size_t n4 = (size_t)N_NODES * D_FEAT / 4;
    int copy_blocks = (int)((n4 + 255) / 256);
    int scat_blocks = (N_EDGES * 32 + 255) / 256;

    size_t tc_smem = (size_t)2 * STAGE_FLOATS * sizeof(float);  // 143360 B
    cudaFuncSetAttribute(gemm_nodes_tc, cudaFuncAttributeMaxDynamicSharedMemorySize,
                         (int)tc_smem);

    dim3 tc_grid((D_FEAT + TC_BN - 1) / TC_BN, (N_NODES + TC_BM - 1) / TC_BM);
    dim3 gemm_pairs_grid((D_OUT + BN - 1) / BN, (2 * N_PAIRS) / BM);

    // layer 1: agg = features + scatter; h1 = lrelu(agg @ W1 + b1)
    copy_to_agg_kernel<<<copy_blocks, 256>>>(features, 1);
    scatter_kernel<<<scat_blocks, 256>>>(features, src, dst, 0);
    gemm_nodes_tc<<<tc_grid, 256, tc_smem>>>(W1, b1, /*out_sel=*/0);

    // layer 2: agg = h1 + scatter(h1); h2 = lrelu(agg @ W2 + b2)
    copy_to_agg_kernel<<<copy_blocks, 256>>>(nullptr, 0);
    scatter_kernel<<<scat_blocks, 256>>>(features, src, dst, 1);
    gemm_nodes_tc<<<tc_grid, 256, tc_smem>>>(W2, b2, /*out_sel=*/1);

    // pair projection + normalize
    gemm_pairs_kernel<<<gemm_pairs_grid, 256>>>(v1, v2, W3, b3);
    normalize_kernel<<<(2 * N_PAIRS * 32 + 255) / 256, 256>>>(out);
}

// round 8
// speedup vs baseline: 1.8809x; 1.0915x over previous
#include <cuda_runtime.h>
#include <math.h>
#include <stdint.h>

#define N_NODES 50000
#define D_FEAT  364
#define D_OUT   150
#define N_PAIRS 8192
#define N_EDGES 200000
#define NEG_SLOPE 0.01f

// Scratch (no cudaMalloc allowed). 16B-aligned for float4.
__device__ __align__(16) float g_agg[(size_t)N_NODES * D_FEAT];
__device__ __align__(16) float g_h1 [(size_t)N_NODES * D_FEAT];
__device__ __align__(16) float g_h2 [(size_t)N_NODES * D_FEAT];
__device__ __align__(16) float g_z  [(size_t)2 * N_PAIRS * D_OUT];

// CSR-by-dst scratch
__device__ int g_deg [N_NODES];
__device__ int g_off [N_NODES];
__device__ int g_pos [N_NODES];
__device__ int g_srcs[N_EDGES];

// ---------------------------------------------------------------------------
// CSR build: zero degrees
__global__ void csr_zero_kernel() {
    int i = blockIdx.x * blockDim.x + threadIdx.x;
    if (i < N_NODES) g_deg[i] = 0;
}
// count in-degree
__global__ void csr_count_kernel(const int* __restrict__ dst) {
    int e = blockIdx.x * blockDim.x + threadIdx.x;
    if (e < N_EDGES) atomicAdd(&g_deg[dst[e]], 1);
}
// exclusive scan over g_deg -> g_off (and g_pos copy). Single block, 1024 thr.
__global__ void csr_scan_kernel() {
    __shared__ int warp_tot[32];
    __shared__ int carry_sh;
    int tid = threadIdx.x;
    int lane = tid & 31, w = tid >> 5;
    if (tid == 0) carry_sh = 0;
    __syncthreads();
    for (int base = 0; base < N_NODES; base += 1024) {
        int i = base + tid;
        int v = (i < N_NODES) ? g_deg[i] : 0;
        int s = v;
        #pragma unroll
        for (int o = 1; o < 32; o <<= 1) {
            int t = __shfl_up_sync(0xFFFFFFFFu, s, o);
            if (lane >= o) s += t;
        }
        if (lane == 31) warp_tot[w] = s;
        __syncthreads();
        if (w == 0) {
            int t = warp_tot[lane];
            int ss = t;
            #pragma unroll
            for (int o = 1; o < 32; o <<= 1) {
                int u = __shfl_up_sync(0xFFFFFFFFu, ss, o);
                if (lane >= o) ss += u;
            }
            warp_tot[lane] = ss - t;   // exclusive warp offset
        }
        __syncthreads();
        int incl = s + warp_tot[w];
        int off  = carry_sh + incl - v;
        if (i < N_NODES) { g_off[i] = off; g_pos[i] = off; }
        __syncthreads();
        if (tid == 1023) carry_sh += incl;   // block total
        __syncthreads();
    }
}
// bucket srcs by dst
__global__ void csr_fill_kernel(const int* __restrict__ src,
                                const int* __restrict__ dst) {
    int e = blockIdx.x * blockDim.x + threadIdx.x;
    if (e >= N_EDGES) return;
    int idx = atomicAdd(&g_pos[dst[e]], 1);
    g_srcs[idx] = src[e];
}

// ---------------------------------------------------------------------------
// gather: g_agg[d] = x[d] + sum_{e: dst(e)=d} x[src(e)].  One warp per node.
__global__ void gather_kernel(const float* __restrict__ x_ext, int layer) {
    int node = (blockIdx.x * blockDim.x + threadIdx.x) >> 5;
    int lane = threadIdx.x & 31;
    if (node >= N_NODES) return;
    const float* __restrict__ x = (layer == 0) ? x_ext : g_h1;
    int off = g_off[node];
    int deg = g_deg[node];
    const float4* xd = reinterpret_cast<const float4*>(x + (size_t)node * D_FEAT);
    bool has2 = lane + 64 < D_FEAT / 4;   // 91 float4 per row
    float4 a0 = xd[lane];
    float4 a1 = xd[lane + 32];
    float4 a2 = has2 ? xd[lane + 64] : make_float4(0.f, 0.f, 0.f, 0.f);
    for (int e = 0; e < deg; e++) {
        int s = g_srcs[off + e];
        const float4* xs = reinterpret_cast<const float4*>(x + (size_t)s * D_FEAT);
        float4 v0 = xs[lane];
        float4 v1 = xs[lane + 32];
        a0.x += v0.x; a0.y += v0.y; a0.z += v0.z; a0.w += v0.w;
        a1.x += v1.x; a1.y += v1.y; a1.z += v1.z; a1.w += v1.w;
        if (has2) {
            float4 v2 = xs[lane + 64];
            a2.x += v2.x; a2.y += v2.y; a2.z += v2.z; a2.w += v2.w;
        }
    }
    float4* ad = reinterpret_cast<float4*>(g_agg + (size_t)node * D_FEAT);
    ad[lane] = a0;
    ad[lane + 32] = a1;
    if (has2) ad[lane + 64] = a2;
}

// ---------------------------------------------------------------------------
// tf32 helpers
__device__ __forceinline__ uint32_t f2tf32(float x) {
    uint32_t r;
    asm("cvt.rna.tf32.f32 %0, %1;" : "=r"(r) : "f"(x));
    return r;
}
__device__ __forceinline__ void split_tf32(float v, float& h, float& l) {
    h = __uint_as_float(f2tf32(v));
    l = __uint_as_float(f2tf32(v - h));
}
__device__ __forceinline__ void mma8(float d[4], const uint32_t a[4], const uint32_t b[2]) {
    asm volatile(
        "mma.sync.aligned.m16n8k8.row.col.f32.tf32.tf32.f32 "
        "{%0,%1,%2,%3}, {%4,%5,%6,%7}, {%8,%9}, {%0,%1,%2,%3};\n"
        : "+f"(d[0]), "+f"(d[1]), "+f"(d[2]), "+f"(d[3])
        : "r"(a[0]), "r"(a[1]), "r"(a[2]), "r"(a[3]), "r"(b[0]), "r"(b[1]));
}

// ---------------------------------------------------------------------------
// out = lrelu(g_agg @ W + b) via 3xTF32 TC GEMM, double-buffered pipeline.
#define TC_BM 128
#define TC_BN 128
#define TC_BK 32
#define AS_STRIDE 36
#define BS_STRIDE 136
#define A_FLOATS (TC_BM * AS_STRIDE)
#define B_FLOATS (TC_BK * BS_STRIDE)
#define STAGE_FLOATS (2 * A_FLOATS + 2 * B_FLOATS)       // 17920
#define NUM_KTILES ((D_FEAT + TC_BK - 1) / TC_BK)        // 12

__global__ __launch_bounds__(256) void gemm_nodes_tc(
        const float* __restrict__ W, const float* __restrict__ bias, int out_sel) {
    const int M = N_NODES, K = D_FEAT, N = D_FEAT;
    float* __restrict__ out = out_sel ? g_h2 : g_h1;

    extern __shared__ float smf[];

    int bm = blockIdx.y * TC_BM;
    int bn = blockIdx.x * TC_BN;
    int tid = threadIdx.x;
    int lane = tid & 31;
    int wid = tid >> 5;
    int wm = (wid & 1) * 64;
    int wn = (wid >> 1) * 32;
    int r = lane >> 2;
    int c = lane & 3;

    float acc[4][4][4];
    #pragma unroll
    for (int i = 0; i < 4; i++)
        #pragma unroll
        for (int j = 0; j < 4; j++)
            #pragma unroll
            for (int q = 0; q < 4; q++) acc[i][j][q] = 0.f;

    int ak4 = tid & 7;
    int arl = tid >> 3;
    int bn4 = tid & 31;
    int bkr = tid >> 5;

    float4 a_pf[4], b_pf[4];

    {
        int gk = ak4 * 4;
        #pragma unroll
        for (int p = 0; p < 4; p++) {
            int gm = bm + p * 32 + arl;
            a_pf[p] = (gm < M && gk < K)
                ? *reinterpret_cast<const float4*>(g_agg + (size_t)gm * K + gk)
                : make_float4(0.f, 0.f, 0.f, 0.f);
        }
        int gn = bn + bn4 * 4;
        #pragma unroll
        for (int p = 0; p < 4; p++) {
            int gkb = p * 8 + bkr;
            b_pf[p] = (gkb < K && gn < N)
                ? *reinterpret_cast<const float4*>(W + (size_t)gkb * N + gn)
                : make_float4(0.f, 0.f, 0.f, 0.f);
        }
    }
    {
        float* As_h = smf;
        float* As_l = smf + A_FLOATS;
        float* Bs_h = smf + 2 * A_FLOATS;
        float* Bs_l = Bs_h + B_FLOATS;
        #pragma unroll
        for (int p = 0; p < 4; p++) {
            int m = p * 32 + arl;
            float4 h, l;
            split_tf32(a_pf[p].x, h.x, l.x);
            split_tf32(a_pf[p].y, h.y, l.y);
            split_tf32(a_pf[p].z, h.z, l.z);
            split_tf32(a_pf[p].w, h.w, l.w);
            *reinterpret_cast<float4*>(As_h + m * AS_STRIDE + ak4 * 4) = h;
            *reinterpret_cast<float4*>(As_l + m * AS_STRIDE + ak4 * 4) = l;
        }
        #pragma unroll
        for (int p = 0; p < 4; p++) {
            int kr = p * 8 + bkr;
            float4 h, l;
            split_tf32(b_pf[p].x, h.x, l.x);
            split_tf32(b_pf[p].y, h.y, l.y);
            split_tf32(b_pf[p].z, h.z, l.z);
            split_tf32(b_pf[p].w, h.w, l.w);
            *reinterpret_cast<float4*>(Bs_h + kr * BS_STRIDE + bn4 * 4) = h;
            *reinterpret_cast<float4*>(Bs_l + kr * BS_STRIDE + bn4 * 4) = l;
        }
    }
    __syncthreads();

    for (int t = 0; t < NUM_KTILES; t++) {
        if (t + 1 < NUM_KTILES) {
            int k0 = (t + 1) * TC_BK;
            int gk = k0 + ak4 * 4;
            #pragma unroll
            for (int p = 0; p < 4; p++) {
                int gm = bm + p * 32 + arl;
                a_pf[p] = (gm < M && gk < K)
                    ? *reinterpret_cast<const float4*>(g_agg + (size_t)gm * K + gk)
                    : make_float4(0.f, 0.f, 0.f, 0.f);
            }
            int gn = bn + bn4 * 4;
            #pragma unroll
            for (int p = 0; p < 4; p++) {
                int gkb = k0 + p * 8 + bkr;
                b_pf[p] = (gkb < K && gn < N)
                    ? *reinterpret_cast<const float4*>(W + (size_t)gkb * N + gn)
                    : make_float4(0.f, 0.f, 0.f, 0.f);
            }
        }
        {
            const float* base = smf + (t & 1) * STAGE_FLOATS;
            const float* As_h = base;
            const float* As_l = base + A_FLOATS;
            const float* Bs_h = base + 2 * A_FLOATS;
            const float* Bs_l = Bs_h + B_FLOATS;

            #pragma unroll
            for (int kk = 0; kk < 4; kk++) {
                uint32_t ah[4][4], al[4][4], bh[4][2], bl[4][2];
                #pragma unroll
                for (int mt = 0; mt < 4; mt++) {
                    int row = wm + mt * 16 + r;
                    const float* ph = As_h + row * AS_STRIDE + kk * 8 + c;
                    const float* pl = As_l + row * AS_STRIDE + kk * 8 + c;
                    ah[mt][0] = __float_as_uint(ph[0]);
                    ah[mt][1] = __float_as_uint(ph[8 * AS_STRIDE]);
                    ah[mt][2] = __float_as_uint(ph[4]);
                    ah[mt][3] = __float_as_uint(ph[8 * AS_STRIDE + 4]);
                    al[mt][0] = __float_as_uint(pl[0]);
                    al[mt][1] = __float_as_uint(pl[8 * AS_STRIDE]);
                    al[mt][2] = __float_as_uint(pl[4]);
                    al[mt][3] = __float_as_uint(pl[8 * AS_STRIDE + 4]);
                }
                #pragma unroll
                for (int nt = 0; nt < 4; nt++) {
                    int col = wn + nt * 8 + r;
                    const float* qh = Bs_h + (kk * 8 + c) * BS_STRIDE + col;
                    const float* ql = Bs_l + (kk * 8 + c) * BS_STRIDE + col;
                    bh[nt][0] = __float_as_uint(qh[0]);
                    bh[nt][1] = __float_as_uint(qh[4 * BS_STRIDE]);
                    bl[nt][0] = __float_as_uint(ql[0]);
                    bl[nt][1] = __float_as_uint(ql[4 * BS_STRIDE]);
                }
                #pragma unroll
                for (int mt = 0; mt < 4; mt++)
                    #pragma unroll
                    for (int nt = 0; nt < 4; nt++) {
                        mma8(acc[mt][nt], ah[mt], bh[nt]);
                        mma8(acc[mt][nt], al[mt], bh[nt]);
                        mma8(acc[mt][nt], ah[mt], bl[nt]);
                    }
            }
        }
        if (t + 1 < NUM_KTILES) {
            float* base = smf + ((t + 1) & 1) * STAGE_FLOATS;
            float* As_h = base;
            float* As_l = base + A_FLOATS;
            float* Bs_h = base + 2 * A_FLOATS;
            float* Bs_l = Bs_h + B_FLOATS;
            #pragma unroll
            for (int p = 0; p < 4; p++) {
                int m = p * 32 + arl;
                float4 h, l;
                split_tf32(a_pf[p].x, h.x, l.x);
                split_tf32(a_pf[p].y, h.y, l.y);
                split_tf32(a_pf[p].z, h.z, l.z);
                split_tf32(a_pf[p].w, h.w, l.w);
                *reinterpret_cast<float4*>(As_h + m * AS_STRIDE + ak4 * 4) = h;
                *reinterpret_cast<float4*>(As_l + m * AS_STRIDE + ak4 * 4) = l;
            }
            #pragma unroll
            for (int p = 0; p < 4; p++) {
                int kr = p * 8 + bkr;
                float4 h, l;
                split_tf32(b_pf[p].x, h.x, l.x);
                split_tf32(b_pf[p].y, h.y, l.y);
                split_tf32(b_pf[p].z, h.z, l.z);
                split_tf32(b_pf[p].w, h.w, l.w);
                *reinterpret_cast<float4*>(Bs_h + kr * BS_STRIDE + bn4 * 4) = h;
                *reinterpret_cast<float4*>(Bs_l + kr * BS_STRIDE + bn4 * 4) = l;
            }
        }
        __syncthreads();
    }

    #pragma unroll
    for (int mt = 0; mt < 4; mt++) {
        int gm0 = bm + wm + mt * 16 + r;
        #pragma unroll
        for (int nt = 0; nt < 4; nt++) {
            int gn = bn + wn + nt * 8 + 2 * c;
            if (gn >= N) continue;
            float b0 = bias[gn], b1 = bias[gn + 1];
            float v0 = acc[mt][nt][0] + b0;
            float v1 = acc[mt][nt][1] + b1;
            float v2 = acc[mt][nt][2] + b0;
            float v3 = acc[mt][nt][3] + b1;
            v0 = v0 > 0.f ? v0 : NEG_SLOPE * v0;
            v1 = v1 > 0.f ? v1 : NEG_SLOPE * v1;
            v2 = v2 > 0.f ? v2 : NEG_SLOPE * v2;
            v3 = v3 > 0.f ? v3 : NEG_SLOPE * v3;
            if (gm0 < M)
                *reinterpret_cast<float2*>(out + (size_t)gm0 * N + gn) = make_float2(v0, v1);
            if (gm0 + 8 < M)
                *reinterpret_cast<float2*>(out + (size_t)(gm0 + 8) * N + gn) = make_float2(v2, v3);
        }
    }
}

// ---------------------------------------------------------------------------
// g_z = lrelu(g_h2[vcat] @ W3 + b3) via 3xTF32 TC. BM=128, BN=64, BK=32.
// 8 warps as 4(m) x 2(n); warp tile 32x32 (mt=2, nt=4). Single-stage smem.
#define P_BN 64
#define PB_STRIDE 72
#define P_A_FLOATS (TC_BM * AS_STRIDE)          // 4608
#define P_B_FLOATS (TC_BK * PB_STRIDE)          // 2304
#define P_SMEM_FLOATS (2 * P_A_FLOATS + 2 * P_B_FLOATS)   // 13824

__global__ __launch_bounds__(256) void gemm_pairs_tc(
        const int* __restrict__ v1, const int* __restrict__ v2,
        const float* __restrict__ W, const float* __restrict__ bias) {
    const int K = D_FEAT, N = D_OUT;

    extern __shared__ float smf[];
    float* As_h = smf;
    float* As_l = smf + P_A_FLOATS;
    float* Bs_h = smf + 2 * P_A_FLOATS;
    float* Bs_l = Bs_h + P_B_FLOATS;
    __shared__ int rows[TC_BM];

    int bm = blockIdx.y * TC_BM;
    int bn = blockIdx.x * P_BN;
    int tid = threadIdx.x;
    int lane = tid & 31;
    int wid = tid >> 5;
    int wm = (wid & 3) * 32;
    int wn = (wid >> 2) * 32;
    int r = lane >> 2;
    int c = lane & 3;

    if (tid < TC_BM) {
        int gm = bm + tid;   // M = 16384 divisible by 128
        rows[tid] = (gm < N_PAIRS) ? v1[gm] : v2[gm - N_PAIRS];
    }
    __syncthreads();

    float acc[2][4][4];
    #pragma unroll
    for (int i = 0; i < 2; i++)
        #pragma unroll
        for (int j = 0; j < 4; j++)
            #pragma unroll
            for (int q = 0; q < 4; q++) acc[i][j][q] = 0.f;

    int ak4 = tid & 7;
    int arl = tid >> 3;
    int bn4 = tid & 15;     // float4 along n (16 per 64-wide row)
    int bkr = tid >> 4;     // 0..15

    for (int k0 = 0; k0 < K; k0 += TC_BK) {
        // A tile (gathered rows)
        #pragma unroll
        for (int p = 0; p < 4; p++) {
            int m = p * 32 + arl;
            int node = rows[m];
            int gk = k0 + ak4 * 4;
            float4 v = (gk < K)
                ? *reinterpret_cast<const float4*>(g_h2 + (size_t)node * K + gk)
                : make_float4(0.f, 0.f, 0.f, 0.f);
            float4 h, l;
            split_tf32(v.x, h.x, l.x);
            split_tf32(v.y, h.y, l.y);
            split_tf32(v.z, h.z, l.z);
            split_tf32(v.w, h.w, l.w);
            *reinterpret_cast<float4*>(As_h + m * AS_STRIDE + ak4 * 4) = h;
            *reinterpret_cast<float4*>(As_l + m * AS_STRIDE + ak4 * 4) = l;
        }
        // B tile [32 x 64] from W3 (row stride 600B -> float2 loads)
        #pragma unroll
        for (int p = 0; p < 2; p++) {
            int kr = p * 16 + bkr;
            int gk = k0 + kr;
            int gn = bn + bn4 * 4;
            float4 v = make_float4(0.f, 0.f, 0.f, 0.f);
            if (gk < K) {
                const float* wrow = W + (size_t)gk * N;
                if (gn + 3 < N) {
                    float2 lo = *reinterpret_cast<const float2*>(wrow + gn);
                    float2 hi = *reinterpret_cast<const float2*>(wrow + gn + 2);
                    v = make_float4(lo.x, lo.y, hi.x, hi.y);
                } else {
                    #pragma unroll
                    for (int j = 0; j < 4; j++) {
                        int nn = gn + j;
                        reinterpret_cast<float*>(&v)[j] = (nn < N) ? wrow[nn] : 0.f;
                    }
                }
            }
            float4 h, l;
            split_tf32(v.x, h.x, l.x);
            split_tf32(v.y, h.y, l.y);
            split_tf32(v.z, h.z, l.z);
            split_tf32(v.w, h.w, l.w);
            *reinterpret_cast<float4*>(Bs_h + kr * PB_STRIDE + bn4 * 4) = h;
            *reinterpret_cast<float4*>(Bs_l + kr * PB_STRIDE + bn4 * 4) = l;
        }
        __syncthreads();

        #pragma unroll
        for (int kk = 0; kk < 4; kk++) {
            uint32_t ah[2][4], al[2][4], bh[4][2], bl[4][2];
            #pragma unroll
            for (int mt = 0; mt < 2; mt++) {
                int row = wm + mt * 16 + r;
                const float* ph = As_h + row * AS_STRIDE + kk * 8 + c;
                const float* pl = As_l + row * AS_STRIDE + kk * 8 + c;
                ah[mt][0] = __float_as_uint(ph[0]);
                ah[mt][1] = __float_as_uint(ph[8 * AS_STRIDE]);
                ah[mt][2] = __float_as_uint(ph[4]);
                ah[mt][3] = __float_as_uint(ph[8 * AS_STRIDE + 4]);
                al[mt][0] = __float_as_uint(pl[0]);
                al[mt][1] = __float_as_uint(pl[8 * AS_STRIDE]);
                al[mt][2] = __float_as_uint(pl[4]);
                al[mt][3] = __float_as_uint(pl[8 * AS_STRIDE + 4]);
            }
            #pragma unroll
            for (int nt = 0; nt < 4; nt++) {
                int col = wn + nt * 8 + r;
                const float* qh = Bs_h + (kk * 8 + c) * PB_STRIDE + col;
                const float* ql = Bs_l + (kk * 8 + c) * PB_STRIDE + col;
                bh[nt][0] = __float_as_uint(qh[0]);
                bh[nt][1] = __float_as_uint(qh[4 * PB_STRIDE]);
                bl[nt][0] = __float_as_uint(ql[0]);
                bl[nt][1] = __float_as_uint(ql[4 * PB_STRIDE]);
            }
            #pragma unroll
            for (int mt = 0; mt < 2; mt++)
                #pragma unroll
                for (int nt = 0; nt < 4; nt++) {
                    mma8(acc[mt][nt], ah[mt], bh[nt]);
                    mma8(acc[mt][nt], al[mt], bh[nt]);
                    mma8(acc[mt][nt], ah[mt], bl[nt]);
                }
        }
        __syncthreads();
    }

    #pragma unroll
    for (int mt = 0; mt < 2; mt++) {
        int gm0 = bm + wm + mt * 16 + r;
        #pragma unroll
        for (int nt = 0; nt < 4; nt++) {
            int gn = bn + wn + nt * 8 + 2 * c;
            if (gn >= N) continue;   // N=150 even, gn even -> float2 in bounds
            float b0 = bias[gn], b1 = bias[gn + 1];
            float v0 = acc[mt][nt][0] + b0;
            float v1 = acc[mt][nt][1] + b1;
            float v2 = acc[mt][nt][2] + b0;
            float v3 = acc[mt][nt][3] + b1;
            v0 = v0 > 0.f ? v0 : NEG_SLOPE * v0;
            v1 = v1 > 0.f ? v1 : NEG_SLOPE * v1;
            v2 = v2 > 0.f ? v2 : NEG_SLOPE * v2;
            v3 = v3 > 0.f ? v3 : NEG_SLOPE * v3;
            *reinterpret_cast<float2*>(g_z + (size_t)gm0 * N + gn) = make_float2(v0, v1);
            *reinterpret_cast<float2*>(g_z + (size_t)(gm0 + 8) * N + gn) = make_float2(v2, v3);
        }
    }
}

// ---------------------------------------------------------------------------
// L2 normalize each row of g_z -> out, one warp per row
__global__ void normalize_kernel(float* __restrict__ out) {
    int row  = (blockIdx.x * blockDim.x + threadIdx.x) >> 5;
    int lane = threadIdx.x & 31;
    if (row >= 2 * N_PAIRS) return;
    const float* zr = g_z + (size_t)row * D_OUT;
    float ss = 0.f;
    for (int i = lane; i < D_OUT; i += 32) { float v = zr[i]; ss += v * v; }
    #pragma unroll
    for (int o = 16; o; o >>= 1) ss += __shfl_xor_sync(0xFFFFFFFFu, ss, o);
    float norm = sqrtf(ss);
    float inv = 1.f / fmaxf(norm, 1e-12f);
    for (int i = lane; i < D_OUT; i += 32) out[(size_t)row * D_OUT + i] = zr[i] * inv;
}

// ---------------------------------------------------------------------------
extern "C" void kernel_launch(void* const* d_in, const int* in_sizes, int n_in,
                              void* d_out, int out_size) {
    const float* features = (const float*)d_in[0];
    const int*   src      = (const int*)  d_in[1];
    const int*   dst      = (const int*)  d_in[2];
    const int*   v1       = (const int*)  d_in[3];
    const int*   v2       = (const int*)  d_in[4];
    const float* W1       = (const float*)d_in[5];
    const float* b1       = (const float*)d_in[6];
    const float* W2       = (const float*)d_in[7];
    const float* b2       = (const float*)d_in[8];
    const float* W3       = (const float*)d_in[9];
    const float* b3       = (const float*)d_in[10];
    float* out = (float*)d_out;
    (void)in_sizes; (void)n_in; (void)out_size;

    size_t tc_smem = (size_t)2 * STAGE_FLOATS * sizeof(float);      // 143360 B
    cudaFuncSetAttribute(gemm_nodes_tc, cudaFuncAttributeMaxDynamicSharedMemorySize,
                         (int)tc_smem);
    size_t p_smem = (size_t)P_SMEM_FLOATS * sizeof(float);          // 55296 B
    cudaFuncSetAttribute(gemm_pairs_tc, cudaFuncAttributeMaxDynamicSharedMemorySize,
                         (int)p_smem);

    dim3 tc_grid((D_FEAT + TC_BN - 1) / TC_BN, (N_NODES + TC_BM - 1) / TC_BM);
    dim3 pairs_grid((D_OUT + P_BN - 1) / P_BN, (2 * N_PAIRS) / TC_BM);
    int gather_blocks = (N_NODES * 32 + 255) / 256;

    // CSR by dst (reused for both layers)
    csr_zero_kernel<<<(N_NODES + 255) / 256, 256>>>();
    csr_count_kernel<<<(N_EDGES + 255) / 256, 256>>>(dst);
    csr_scan_kernel<<<1, 1024>>>();
    csr_fill_kernel<<<(N_EDGES + 255) / 256, 256>>>(src, dst);

    // layer 1: agg = features[d] + sum_in features[src]; h1 = lrelu(agg @ W1 + b1)
    gather_kernel<<<gather_blocks, 256>>>(features, 0);
    gemm_nodes_tc<<<tc_grid, 256, tc_smem>>>(W1, b1, /*out_sel=*/0);

    // layer 2: agg = h1[d] + sum_in h1[src]; h2 = lrelu(agg @ W2 + b2)
    gather_kernel<<<gather_blocks, 256>>>(nullptr, 1);
    gemm_nodes_tc<<<tc_grid, 256, tc_smem>>>(W2, b2, /*out_sel=*/1);

    // pair projection + normalize
    gemm_pairs_tc<<<pairs_grid, 256, p_smem>>>(v1, v2, W3, b3);
    normalize_kernel<<<(2 * N_PAIRS * 32 + 255) / 256, 256>>>(out);
}

// round 9
// speedup vs baseline: 2.6070x; 1.3860x over previous
#include <cuda_runtime.h>
#include <cuda_bf16.h>
#include <math.h>
#include <stdint.h>

#define N_NODES 50000
#define D_FEAT  364
#define D_OUT   150
#define N_PAIRS 8192
#define N_EDGES 200000
#define NEG_SLOPE 0.01f

#define AKP 192          // padded kp (k/2) per row for A (K padded to 384)
#define WB_NS 384        // padded n stride for converted W

// Scratch (no cudaMalloc allowed).
__device__ __align__(16) float g_h1 [(size_t)N_NODES * D_FEAT];
__device__ __align__(16) float g_h2 [(size_t)N_NODES * D_FEAT];
__device__ __align__(16) float g_z  [(size_t)2 * N_PAIRS * D_OUT];
// bf16-split A (agg) and W, packed bf16x2 along k (uint32 = {k even lo, k odd hi})
__device__ __align__(16) uint32_t g_agg_h[(size_t)N_NODES * AKP];
__device__ __align__(16) uint32_t g_agg_l[(size_t)N_NODES * AKP];
__device__ __align__(16) uint32_t g_wb_h [(size_t)AKP * WB_NS];   // [kp][n]
__device__ __align__(16) uint32_t g_wb_l [(size_t)AKP * WB_NS];

// CSR-by-dst scratch
__device__ int g_deg [N_NODES];
__device__ int g_off [N_NODES];
__device__ int g_pos [N_NODES];
__device__ int g_srcs[N_EDGES];

// ---------------------------------------------------------------------------
// bf16 split helpers
__device__ __forceinline__ void split1(float v, __nv_bfloat16& h, __nv_bfloat16& l) {
    h = __float2bfloat16_rn(v);
    l = __float2bfloat16_rn(v - __bfloat162float(h));
}
__device__ __forceinline__ uint32_t pack2(__nv_bfloat16 lo, __nv_bfloat16 hi) {
    __nv_bfloat162 p;
    p.x = lo; p.y = hi;
    return *reinterpret_cast<uint32_t*>(&p);
}

// ---------------------------------------------------------------------------
// CSR build
__global__ void csr_zero_kernel() {
    int i = blockIdx.x * blockDim.x + threadIdx.x;
    if (i < N_NODES) g_deg[i] = 0;
}
__global__ void csr_count_kernel(const int* __restrict__ dst) {
    int e = blockIdx.x * blockDim.x + threadIdx.x;
    if (e < N_EDGES) atomicAdd(&g_deg[dst[e]], 1);
}
__global__ void csr_scan_kernel() {
    __shared__ int warp_tot[32];
    __shared__ int carry_sh;
    int tid = threadIdx.x;
    int lane = tid & 31, w = tid >> 5;
    if (tid == 0) carry_sh = 0;
    __syncthreads();
    for (int base = 0; base < N_NODES; base += 1024) {
        int i = base + tid;
        int v = (i < N_NODES) ? g_deg[i] : 0;
        int s = v;
        #pragma unroll
        for (int o = 1; o < 32; o <<= 1) {
            int t = __shfl_up_sync(0xFFFFFFFFu, s, o);
            if (lane >= o) s += t;
        }
        if (lane == 31) warp_tot[w] = s;
        __syncthreads();
        if (w == 0) {
            int t = warp_tot[lane];
            int ss = t;
            #pragma unroll
            for (int o = 1; o < 32; o <<= 1) {
                int u = __shfl_up_sync(0xFFFFFFFFu, ss, o);
                if (lane >= o) ss += u;
            }
            warp_tot[lane] = ss - t;
        }
        __syncthreads();
        int incl = s + warp_tot[w];
        int off  = carry_sh + incl - v;
        if (i < N_NODES) { g_off[i] = off; g_pos[i] = off; }
        __syncthreads();
        if (tid == 1023) carry_sh += incl;
        __syncthreads();
    }
}
__global__ void csr_fill_kernel(const int* __restrict__ src,
                                const int* __restrict__ dst) {
    int e = blockIdx.x * blockDim.x + threadIdx.x;
    if (e >= N_EDGES) return;
    int idx = atomicAdd(&g_pos[dst[e]], 1);
    g_srcs[idx] = src[e];
}

// ---------------------------------------------------------------------------
// gather + bf16 split: agg = x[d] + sum_in x[src]; emit g_agg_h/l packed pairs.
__global__ void gather_kernel(const float* __restrict__ x_ext, int layer) {
    int node = (blockIdx.x * blockDim.x + threadIdx.x) >> 5;
    int lane = threadIdx.x & 31;
    if (node >= N_NODES) return;
    const float* __restrict__ x = (layer == 0) ? x_ext : g_h1;
    int off = g_off[node];
    int deg = g_deg[node];
    const float4* xd = reinterpret_cast<const float4*>(x + (size_t)node * D_FEAT);
    bool has2 = lane + 64 < D_FEAT / 4;   // 91 float4 per row
    float4 a0 = xd[lane];
    float4 a1 = xd[lane + 32];
    float4 a2 = has2 ? xd[lane + 64] : make_float4(0.f, 0.f, 0.f, 0.f);
    for (int e = 0; e < deg; e++) {
        int s = g_srcs[off + e];
        const float4* xs = reinterpret_cast<const float4*>(x + (size_t)s * D_FEAT);
        float4 v0 = xs[lane];
        float4 v1 = xs[lane + 32];
        a0.x += v0.x; a0.y += v0.y; a0.z += v0.z; a0.w += v0.w;
        a1.x += v1.x; a1.y += v1.y; a1.z += v1.z; a1.w += v1.w;
        if (has2) {
            float4 v2 = xs[lane + 64];
            a2.x += v2.x; a2.y += v2.y; a2.z += v2.z; a2.w += v2.w;
        }
    }
    // split & pack: float4 at k4 index covers k = 4*k4.. -> kp = 2*k4, 2*k4+1
    uint32_t* oh = g_agg_h + (size_t)node * AKP;
    uint32_t* ol = g_agg_l + (size_t)node * AKP;
    float4 chunks[3] = {a0, a1, a2};
    #pragma unroll
    for (int i = 0; i < 3; i++) {
        int k4 = lane + 32 * i;
        float4 v = chunks[i];
        bool valid = (i < 2) || has2;
        if (!valid) v = make_float4(0.f, 0.f, 0.f, 0.f);
        __nv_bfloat16 hx, lx, hy, ly, hz, lz, hw, lw;
        split1(v.x, hx, lx); split1(v.y, hy, ly);
        split1(v.z, hz, lz); split1(v.w, hw, lw);
        uint2 ph = make_uint2(pack2(hx, hy), pack2(hz, hw));
        uint2 pl = make_uint2(pack2(lx, ly), pack2(lz, lw));
        *reinterpret_cast<uint2*>(oh + 2 * k4) = ph;
        *reinterpret_cast<uint2*>(ol + 2 * k4) = pl;
    }
}

// ---------------------------------------------------------------------------
// convert W [K x N] fp32 -> g_wb_h/l: [kp][n] packed bf16x2 of (W[2kp][n], W[2kp+1][n])
__global__ void convert_w_kernel(const float* __restrict__ W) {
    int idx = blockIdx.x * blockDim.x + threadIdx.x;      // 192 * 96 threads
    int kp = idx / (WB_NS / 4);
    int nq = idx % (WB_NS / 4);
    if (kp >= AKP) return;
    int n0 = nq * 4;
    uint32_t oh[4], ol[4];
    #pragma unroll
    for (int j = 0; j < 4; j++) {
        int n = n0 + j;
        float v0 = 0.f, v1 = 0.f;
        if (2 * kp < D_FEAT && n < D_FEAT) {
            v0 = W[(size_t)(2 * kp) * D_FEAT + n];
            v1 = W[(size_t)(2 * kp + 1) * D_FEAT + n];
        }
        __nv_bfloat16 h0, l0, h1, l1;
        split1(v0, h0, l0);
        split1(v1, h1, l1);
        oh[j] = pack2(h0, h1);    // lo = k even, hi = k odd
        ol[j] = pack2(l0, l1);
    }
    size_t o = (size_t)kp * WB_NS + n0;
    *reinterpret_cast<uint4*>(g_wb_h + o) = make_uint4(oh[0], oh[1], oh[2], oh[3]);
    *reinterpret_cast<uint4*>(g_wb_l + o) = make_uint4(ol[0], ol[1], ol[2], ol[3]);
}

// ---------------------------------------------------------------------------
// bf16 m16n8k16 mma
__device__ __forceinline__ void mma16(float d[4], const uint32_t a[4], const uint32_t b[2]) {
    asm volatile(
        "mma.sync.aligned.m16n8k16.row.col.f32.bf16.bf16.f32 "
        "{%0,%1,%2,%3}, {%4,%5,%6,%7}, {%8,%9}, {%0,%1,%2,%3};\n"
        : "+f"(d[0]), "+f"(d[1]), "+f"(d[2]), "+f"(d[3])
        : "r"(a[0]), "r"(a[1]), "r"(a[2]), "r"(a[3]), "r"(b[0]), "r"(b[1]));
}

// ---------------------------------------------------------------------------
// node GEMM: out = lrelu(agg @ W + b), bf16x3, pipelined double buffer.
// BM=128, BN=128, BK=32 (16 kp). 8 warps 2(m) x 4(n), warp tile 64x32.
#define TC_BM 128
#define TC_BN 128
#define AS2 36          // uint32 stride, ==4 mod 32 -> frag conflict-free
#define BS2 136         // uint32 stride, ==8 mod 32
#define A_U32 (TC_BM * AS2)              // 4608
#define B_U32 (16 * BS2)                 // 2176
#define STAGE_U32 (2 * A_U32 + 2 * B_U32)   // 13568
#define NUM_KT 12       // 12 * 16 kp = 192 = AKP

__global__ __launch_bounds__(256) void gemm_nodes_tc(
        const float* __restrict__ bias, int out_sel) {
    const int M = N_NODES, N = D_FEAT;
    float* __restrict__ out = out_sel ? g_h2 : g_h1;

    extern __shared__ uint32_t smu[];

    int bm = blockIdx.y * TC_BM;
    int bn = blockIdx.x * TC_BN;
    int tid = threadIdx.x;
    int lane = tid & 31;
    int wid = tid >> 5;
    int wm = (wid & 1) * 64;
    int wn = (wid >> 1) * 32;
    int r = lane >> 2;
    int c = lane & 3;

    float acc[4][4][4];
    #pragma unroll
    for (int i = 0; i < 4; i++)
        #pragma unroll
        for (int j = 0; j < 4; j++)
            #pragma unroll
            for (int q = 0; q < 4; q++) acc[i][j][q] = 0.f;

    // A load map: 2 passes, row = p*64 + (tid>>2), q4 = tid&3 (uint4 along kp)
    int a_row = tid >> 2;     // 0..63
    int a_q4  = tid & 3;
    // B load map: 2 passes, kp_l = p*8 + (tid>>5), n4 = tid&31
    int b_kp = tid >> 5;      // 0..7
    int b_n4 = tid & 31;

    uint4 apf_h[2], apf_l[2], bpf_h[2], bpf_l[2];

    auto load_tile = [&](int t) {
        int kp0 = t * 16;
        #pragma unroll
        for (int p = 0; p < 2; p++) {
            int gm = bm + p * 64 + a_row;
            if (gm < M) {
                size_t o = (size_t)gm * AKP + kp0 + a_q4 * 4;
                apf_h[p] = *reinterpret_cast<const uint4*>(g_agg_h + o);
                apf_l[p] = *reinterpret_cast<const uint4*>(g_agg_l + o);
            } else {
                apf_h[p] = make_uint4(0, 0, 0, 0);
                apf_l[p] = make_uint4(0, 0, 0, 0);
            }
        }
        #pragma unroll
        for (int p = 0; p < 2; p++) {
            size_t o = (size_t)(kp0 + p * 8 + b_kp) * WB_NS + bn + b_n4 * 4;
            bpf_h[p] = *reinterpret_cast<const uint4*>(g_wb_h + o);
            bpf_l[p] = *reinterpret_cast<const uint4*>(g_wb_l + o);
        }
    };
    auto store_tile = [&](int stage) {
        uint32_t* base = smu + stage * STAGE_U32;
        uint32_t* As_h = base;
        uint32_t* As_l = base + A_U32;
        uint32_t* Bs_h = base + 2 * A_U32;
        uint32_t* Bs_l = Bs_h + B_U32;
        #pragma unroll
        for (int p = 0; p < 2; p++) {
            int m = p * 64 + a_row;
            *reinterpret_cast<uint4*>(As_h + m * AS2 + a_q4 * 4) = apf_h[p];
            *reinterpret_cast<uint4*>(As_l + m * AS2 + a_q4 * 4) = apf_l[p];
        }
        #pragma unroll
        for (int p = 0; p < 2; p++) {
            int kp = p * 8 + b_kp;
            *reinterpret_cast<uint4*>(Bs_h + kp * BS2 + b_n4 * 4) = bpf_h[p];
            *reinterpret_cast<uint4*>(Bs_l + kp * BS2 + b_n4 * 4) = bpf_l[p];
        }
    };

    load_tile(0);
    store_tile(0);
    __syncthreads();

    for (int t = 0; t < NUM_KT; t++) {
        if (t + 1 < NUM_KT) load_tile(t + 1);

        {
            const uint32_t* base = smu + (t & 1) * STAGE_U32;
            const uint32_t* As_h = base;
            const uint32_t* As_l = base + A_U32;
            const uint32_t* Bs_h = base + 2 * A_U32;
            const uint32_t* Bs_l = Bs_h + B_U32;

            #pragma unroll
            for (int kk = 0; kk < 2; kk++) {     // 2 x k16 per BK=32
                uint32_t ah[4][4], al[4][4], bh[4][2], bl[4][2];
                #pragma unroll
                for (int mt = 0; mt < 4; mt++) {
                    int row = wm + mt * 16 + r;
                    const uint32_t* ph = As_h + row * AS2 + kk * 8 + c;
                    const uint32_t* pl = As_l + row * AS2 + kk * 8 + c;
                    ah[mt][0] = ph[0];
                    ah[mt][1] = ph[8 * AS2];
                    ah[mt][2] = ph[4];
                    ah[mt][3] = ph[8 * AS2 + 4];
                    al[mt][0] = pl[0];
                    al[mt][1] = pl[8 * AS2];
                    al[mt][2] = pl[4];
                    al[mt][3] = pl[8 * AS2 + 4];
                }
                #pragma unroll
                for (int nt = 0; nt < 4; nt++) {
                    int col = wn + nt * 8 + r;
                    const uint32_t* qh = Bs_h + (kk * 8 + c) * BS2 + col;
                    const uint32_t* ql = Bs_l + (kk * 8 + c) * BS2 + col;
                    bh[nt][0] = qh[0];
                    bh[nt][1] = qh[4 * BS2];
                    bl[nt][0] = ql[0];
                    bl[nt][1] = ql[4 * BS2];
                }
                #pragma unroll
                for (int mt = 0; mt < 4; mt++)
                    #pragma unroll
                    for (int nt = 0; nt < 4; nt++) {
                        mma16(acc[mt][nt], ah[mt], bh[nt]);   // hi*hi
                        mma16(acc[mt][nt], al[mt], bh[nt]);   // lo*hi
                        mma16(acc[mt][nt], ah[mt], bl[nt]);   // hi*lo
                    }
            }
        }

        if (t + 1 < NUM_KT) store_tile((t + 1) & 1);
        __syncthreads();
    }

    // epilogue: bias + leaky relu, float2 stores
    #pragma unroll
    for (int mt = 0; mt < 4; mt++) {
        int gm0 = bm + wm + mt * 16 + r;
        #pragma unroll
        for (int nt = 0; nt < 4; nt++) {
            int gn = bn + wn + nt * 8 + 2 * c;
            if (gn >= N) continue;
            float b0 = bias[gn], b1 = bias[gn + 1];
            float v0 = acc[mt][nt][0] + b0;
            float v1 = acc[mt][nt][1] + b1;
            float v2 = acc[mt][nt][2] + b0;
            float v3 = acc[mt][nt][3] + b1;
            v0 = v0 > 0.f ? v0 : NEG_SLOPE * v0;
            v1 = v1 > 0.f ? v1 : NEG_SLOPE * v1;
            v2 = v2 > 0.f ? v2 : NEG_SLOPE * v2;
            v3 = v3 > 0.f ? v3 : NEG_SLOPE * v3;
            if (gm0 < M)
                *reinterpret_cast<float2*>(out + (size_t)gm0 * N + gn) = make_float2(v0, v1);
            if (gm0 + 8 < M)
                *reinterpret_cast<float2*>(out + (size_t)(gm0 + 8) * N + gn) = make_float2(v2, v3);
        }
    }
}

// ---------------------------------------------------------------------------
// tf32 helpers for pairs GEMM
__device__ __forceinline__ uint32_t f2tf32(float x) {
    uint32_t r;
    asm("cvt.rna.tf32.f32 %0, %1;" : "=r"(r) : "f"(x));
    return r;
}
__device__ __forceinline__ void split_tf32(float v, float& h, float& l) {
    h = __uint_as_float(f2tf32(v));
    l = __uint_as_float(f2tf32(v - h));
}
__device__ __forceinline__ void mma8(float d[4], const uint32_t a[4], const uint32_t b[2]) {
    asm volatile(
        "mma.sync.aligned.m16n8k8.row.col.f32.tf32.tf32.f32 "
        "{%0,%1,%2,%3}, {%4,%5,%6,%7}, {%8,%9}, {%0,%1,%2,%3};\n"
        : "+f"(d[0]), "+f"(d[1]), "+f"(d[2]), "+f"(d[3])
        : "r"(a[0]), "r"(a[1]), "r"(a[2]), "r"(a[3]), "r"(b[0]), "r"(b[1]));
}

// ---------------------------------------------------------------------------
// pairs GEMM (tf32x3): g_z = lrelu(g_h2[vcat] @ W3 + b3)
#define P_BN 64
#define P_BK 32
#define PAS 36
#define PBS 72
#define P_A_FLOATS (TC_BM * PAS)
#define P_B_FLOATS (P_BK * PBS)
#define P_SMEM_FLOATS (2 * P_A_FLOATS + 2 * P_B_FLOATS)

__global__ __launch_bounds__(256) void gemm_pairs_tc(
        const int* __restrict__ v1, const int* __restrict__ v2,
        const float* __restrict__ W, const float* __restrict__ bias) {
    const int K = D_FEAT, N = D_OUT;

    extern __shared__ float smf[];
    float* As_h = smf;
    float* As_l = smf + P_A_FLOATS;
    float* Bs_h = smf + 2 * P_A_FLOATS;
    float* Bs_l = Bs_h + P_B_FLOATS;
    __shared__ int rows[TC_BM];

    int bm = blockIdx.y * TC_BM;
    int bn = blockIdx.x * P_BN;
    int tid = threadIdx.x;
    int lane = tid & 31;
    int wid = tid >> 5;
    int wm = (wid & 3) * 32;
    int wn = (wid >> 2) * 32;
    int r = lane >> 2;
    int c = lane & 3;

    if (tid < TC_BM) {
        int gm = bm + tid;
        rows[tid] = (gm < N_PAIRS) ? v1[gm] : v2[gm - N_PAIRS];
    }
    __syncthreads();

    float acc[2][4][4];
    #pragma unroll
    for (int i = 0; i < 2; i++)
        #pragma unroll
        for (int j = 0; j < 4; j++)
            #pragma unroll
            for (int q = 0; q < 4; q++) acc[i][j][q] = 0.f;

    int ak4 = tid & 7;
    int arl = tid >> 3;
    int bn4 = tid & 15;
    int bkr = tid >> 4;

    for (int k0 = 0; k0 < K; k0 += P_BK) {
        #pragma unroll
        for (int p = 0; p < 4; p++) {
            int m = p * 32 + arl;
            int node = rows[m];
            int gk = k0 + ak4 * 4;
            float4 v = (gk < K)
                ? *reinterpret_cast<const float4*>(g_h2 + (size_t)node * K + gk)
                : make_float4(0.f, 0.f, 0.f, 0.f);
            float4 h, l;
            split_tf32(v.x, h.x, l.x);
            split_tf32(v.y, h.y, l.y);
            split_tf32(v.z, h.z, l.z);
            split_tf32(v.w, h.w, l.w);
            *reinterpret_cast<float4*>(As_h + m * PAS + ak4 * 4) = h;
            *reinterpret_cast<float4*>(As_l + m * PAS + ak4 * 4) = l;
        }
        #pragma unroll
        for (int p = 0; p < 2; p++) {
            int kr = p * 16 + bkr;
            int gk = k0 + kr;
            int gn = bn + bn4 * 4;
            float4 v = make_float4(0.f, 0.f, 0.f, 0.f);
            if (gk < K) {
                const float* wrow = W + (size_t)gk * N;
                if (gn + 3 < N) {
                    float2 lo = *reinterpret_cast<const float2*>(wrow + gn);
                    float2 hi = *reinterpret_cast<const float2*>(wrow + gn + 2);
                    v = make_float4(lo.x, lo.y, hi.x, hi.y);
                } else {
                    #pragma unroll
                    for (int j = 0; j < 4; j++) {
                        int nn = gn + j;
                        reinterpret_cast<float*>(&v)[j] = (nn < N) ? wrow[nn] : 0.f;
                    }
                }
            }
            float4 h, l;
            split_tf32(v.x, h.x, l.x);
            split_tf32(v.y, h.y, l.y);
            split_tf32(v.z, h.z, l.z);
            split_tf32(v.w, h.w, l.w);
            *reinterpret_cast<float4*>(Bs_h + kr * PBS + bn4 * 4) = h;
            *reinterpret_cast<float4*>(Bs_l + kr * PBS + bn4 * 4) = l;
        }
        __syncthreads();

        #pragma unroll
        for (int kk = 0; kk < 4; kk++) {
            uint32_t ah[2][4], al[2][4], bh[4][2], bl[4][2];
            #pragma unroll
            for (int mt = 0; mt < 2; mt++) {
                int row = wm + mt * 16 + r;
                const float* ph = As_h + row * PAS + kk * 8 + c;
                const float* pl = As_l + row * PAS + kk * 8 + c;
                ah[mt][0] = __float_as_uint(ph[0]);
                ah[mt][1] = __float_as_uint(ph[8 * PAS]);
                ah[mt][2] = __float_as_uint(ph[4]);
                ah[mt][3] = __float_as_uint(ph[8 * PAS + 4]);
                al[mt][0] = __float_as_uint(pl[0]);
                al[mt][1] = __float_as_uint(pl[8 * PAS]);
                al[mt][2] = __float_as_uint(pl[4]);
                al[mt][3] = __float_as_uint(pl[8 * PAS + 4]);
            }
            #pragma unroll
            for (int nt = 0; nt < 4; nt++) {
                int col = wn + nt * 8 + r;
                const float* qh = Bs_h + (kk * 8 + c) * PBS + col;
                const float* ql = Bs_l + (kk * 8 + c) * PBS + col;
                bh[nt][0] = __float_as_uint(qh[0]);
                bh[nt][1] = __float_as_uint(qh[4 * PBS]);
                bl[nt][0] = __float_as_uint(ql[0]);
                bl[nt][1] = __float_as_uint(ql[4 * PBS]);
            }
            #pragma unroll
            for (int mt = 0; mt < 2; mt++)
                #pragma unroll
                for (int nt = 0; nt < 4; nt++) {
                    mma8(acc[mt][nt], ah[mt], bh[nt]);
                    mma8(acc[mt][nt], al[mt], bh[nt]);
                    mma8(acc[mt][nt], ah[mt], bl[nt]);
                }
        }
        __syncthreads();
    }

    #pragma unroll
    for (int mt = 0; mt < 2; mt++) {
        int gm0 = bm + wm + mt * 16 + r;
        #pragma unroll
        for (int nt = 0; nt < 4; nt++) {
            int gn = bn + wn + nt * 8 + 2 * c;
            if (gn >= N) continue;
            float b0 = bias[gn], b1 = bias[gn + 1];
            float v0 = acc[mt][nt][0] + b0;
            float v1 = acc[mt][nt][1] + b1;
            float v2 = acc[mt][nt][2] + b0;
            float v3 = acc[mt][nt][3] + b1;
            v0 = v0 > 0.f ? v0 : NEG_SLOPE * v0;
            v1 = v1 > 0.f ? v1 : NEG_SLOPE * v1;
            v2 = v2 > 0.f ? v2 : NEG_SLOPE * v2;
            v3 = v3 > 0.f ? v3 : NEG_SLOPE * v3;
            *reinterpret_cast<float2*>(g_z + (size_t)gm0 * N + gn) = make_float2(v0, v1);
            *reinterpret_cast<float2*>(g_z + (size_t)(gm0 + 8) * N + gn) = make_float2(v2, v3);
        }
    }
}

// ---------------------------------------------------------------------------
// L2 normalize
__global__ void normalize_kernel(float* __restrict__ out) {
    int row  = (blockIdx.x * blockDim.x + threadIdx.x) >> 5;
    int lane = threadIdx.x & 31;
    if (row >= 2 * N_PAIRS) return;
    const float* zr = g_z + (size_t)row * D_OUT;
    float ss = 0.f;
    for (int i = lane; i < D_OUT; i += 32) { float v = zr[i]; ss += v * v; }
    #pragma unroll
    for (int o = 16; o; o >>= 1) ss += __shfl_xor_sync(0xFFFFFFFFu, ss, o);
    float norm = sqrtf(ss);
    float inv = 1.f / fmaxf(norm, 1e-12f);
    for (int i = lane; i < D_OUT; i += 32) out[(size_t)row * D_OUT + i] = zr[i] * inv;
}

// ---------------------------------------------------------------------------
extern "C" void kernel_launch(void* const* d_in, const int* in_sizes, int n_in,
                              void* d_out, int out_size) {
    const float* features = (const float*)d_in[0];
    const int*   src      = (const int*)  d_in[1];
    const int*   dst      = (const int*)  d_in[2];
    const int*   v1       = (const int*)  d_in[3];
    const int*   v2       = (const int*)  d_in[4];
    const float* W1       = (const float*)d_in[5];
    const float* b1       = (const float*)d_in[6];
    const float* W2       = (const float*)d_in[7];
    const float* b2       = (const float*)d_in[8];
    const float* W3       = (const float*)d_in[9];
    const float* b3       = (const float*)d_in[10];
    float* out = (float*)d_out;
    (void)in_sizes; (void)n_in; (void)out_size;

    size_t tc_smem = (size_t)2 * STAGE_U32 * sizeof(uint32_t);      // 108544 B
    cudaFuncSetAttribute(gemm_nodes_tc, cudaFuncAttributeMaxDynamicSharedMemorySize,
                         (int)tc_smem);
    size_t p_smem = (size_t)P_SMEM_FLOATS * sizeof(float);
    cudaFuncSetAttribute(gemm_pairs_tc, cudaFuncAttributeMaxDynamicSharedMemorySize,
                         (int)p_smem);

    dim3 tc_grid((D_FEAT + TC_BN - 1) / TC_BN, (N_NODES + TC_BM - 1) / TC_BM);
    dim3 pairs_grid((D_OUT + P_BN - 1) / P_BN, (2 * N_PAIRS) / TC_BM);
    int gather_blocks = (N_NODES * 32 + 255) / 256;
    int convw_blocks = (AKP * (WB_NS / 4) + 255) / 256;

    // CSR by dst (reused for both layers)
    csr_zero_kernel<<<(N_NODES + 255) / 256, 256>>>();
    csr_count_kernel<<<(N_EDGES + 255) / 256, 256>>>(dst);
    csr_scan_kernel<<<1, 1024>>>();
    csr_fill_kernel<<<(N_EDGES + 255) / 256, 256>>>(src, dst);

    // layer 1
    convert_w_kernel<<<convw_blocks, 256>>>(W1);
    gather_kernel<<<gather_blocks, 256>>>(features, 0);
    gemm_nodes_tc<<<tc_grid, 256, tc_smem>>>(b1, /*out_sel=*/0);

    // layer 2 (convert W2 overwrites wb AFTER gemm1 consumed it; sequential stream)
    convert_w_kernel<<<convw_blocks, 256>>>(W2);
    gather_kernel<<<gather_blocks, 256>>>(nullptr, 1);
    gemm_nodes_tc<<<tc_grid, 256, tc_smem>>>(b2, /*out_sel=*/1);

    // pair projection + normalize
    gemm_pairs_tc<<<pairs_grid, 256, p_smem>>>(v1, v2, W3, b3);
    normalize_kernel<<<(2 * N_PAIRS * 32 + 255) / 256, 256>>>(out);
}